// round 3
// baseline (speedup 1.0000x reference)
#include <cuda_runtime.h>
#include <math.h>

#define NN 100000
#define EE 1600000
#define FIN 512
#define HH 128
#define KKEEP 50000
#define NCH 98  // ceil(NN/1024)

typedef unsigned long long ull;

// ------------------------- device scratch (globals) -------------------------
__device__ __align__(16) float g_y [(size_t)NN * HH];   // scaled xw buffer (y = ds * X@W)
__device__ __align__(16) float g_x1[(size_t)NN * HH];
__device__ __align__(16) float g_x2[(size_t)NN * HH];
__device__ __align__(16) float g_x3[(size_t)NN * HH];
__device__ float g_ds[NN];
__device__ int   g_degcnt[NN];
__device__ int   g_rowptr[NN + 1];
__device__ int   g_fill[NN];
__device__ int   g_csr[EE];
__device__ int   g_chunksum[NCH];
__device__ int   g_chunkoff[NCH];
__device__ float g_ysc[NN];       // scaled score lin
__device__ float g_score[NN];
__device__ unsigned g_ukey[NN];
__device__ unsigned g_hist[256];
__device__ unsigned g_prefix;
__device__ unsigned g_kprime;
__device__ int   g_nties;
__device__ int   g_tieidx[NN];
__device__ int   g_tieflag[NN];
__device__ float g_gmax[384];
__device__ float g_gsum[384];

// ------------------------- small helpers -------------------------
__device__ __forceinline__ void ffma2(ull &d, ull a, ull b) {
    asm("fma.rn.f32x2 %0, %1, %2, %0;" : "+l"(d) : "l"(a), "l"(b));
}
__device__ __forceinline__ ull pack2(float lo, float hi) {
    ull r;
    asm("mov.b64 %0, {%1, %2};" : "=l"(r) : "r"(__float_as_uint(lo)), "r"(__float_as_uint(hi)));
    return r;
}
__device__ __forceinline__ void unpack2(ull p, float &lo, float &hi) {
    unsigned a, b;
    asm("mov.b64 {%0, %1}, %2;" : "=r"(a), "=r"(b) : "l"(p));
    lo = __uint_as_float(a); hi = __uint_as_float(b);
}
__device__ __forceinline__ unsigned fkey(float f) {
    unsigned u = __float_as_uint(f);
    return (u & 0x80000000u) ? ~u : (u | 0x80000000u);  // monotone: bigger float -> bigger key
}
__device__ __forceinline__ void atomicMaxF(float *addr, float val) {
    if (val >= 0.f) atomicMax((int *)addr, __float_as_int(val));
    else            atomicMin((unsigned *)addr, __float_as_uint(val));
}
__device__ __forceinline__ const float *pickX(int w) {
    return w == 1 ? g_x1 : (w == 2 ? g_x2 : g_x3);
}

// ------------------------- init -------------------------
__global__ void k_init() {
    int i = blockIdx.x * blockDim.x + threadIdx.x;
    if (i < NN) { g_degcnt[i] = 0; g_fill[i] = 0; g_tieflag[i] = 0; }
    if (i < 384) { g_gmax[i] = -3.402823466e38f; g_gsum[i] = 0.f; }
    if (i < 256) g_hist[i] = 0u;
    if (i == 0) { g_prefix = 0u; g_kprime = (unsigned)KKEEP; g_nties = 0; }
}

// ------------------------- degree / CSR build (edge_index is int32) -------------------------
__global__ void k_count(const int *__restrict__ ei) {
    int e4 = blockIdx.x * blockDim.x + threadIdx.x;
    if (e4 >= EE / 4) return;
    int4 d = *(const int4 *)&ei[EE + e4 * 4];
    atomicAdd(&g_degcnt[d.x], 1);
    atomicAdd(&g_degcnt[d.y], 1);
    atomicAdd(&g_degcnt[d.z], 1);
    atomicAdd(&g_degcnt[d.w], 1);
}
__global__ void k_node() {
    int i = blockIdx.x * blockDim.x + threadIdx.x;
    if (i >= NN) return;
    g_ds[i] = rsqrtf((float)(g_degcnt[i] + 1));
}
__global__ void k_chunksum() {
    __shared__ int sm[256];
    int t = threadIdx.x, b = blockIdx.x;
    int s = 0;
    for (int j = t; j < 1024; j += 256) {
        int idx = b * 1024 + j;
        if (idx < NN) s += g_degcnt[idx];
    }
    sm[t] = s; __syncthreads();
    for (int o = 128; o; o >>= 1) { if (t < o) sm[t] += sm[t + o]; __syncthreads(); }
    if (t == 0) g_chunksum[b] = sm[0];
}
__global__ void k_scanchunks() {
    int run = 0;
    for (int c = 0; c < NCH; ++c) { g_chunkoff[c] = run; run += g_chunksum[c]; }
    g_rowptr[NN] = EE;
}
__global__ void k_scanwrite() {
    __shared__ int sd[1024];
    int t = threadIdx.x, b = blockIdx.x;
    int idx = b * 1024 + t;
    int v = (idx < NN) ? g_degcnt[idx] : 0;
    int x = v;
    for (int o = 1; o < 1024; o <<= 1) {
        sd[t] = x; __syncthreads();
        if (t >= o) x += sd[t - o];
        __syncthreads();
    }
    if (idx < NN) g_rowptr[idx] = g_chunkoff[b] + x - v;
}
__global__ void k_scatter(const int *__restrict__ ei) {
    int e4 = blockIdx.x * blockDim.x + threadIdx.x;
    if (e4 >= EE / 4) return;
    int4 s = *(const int4 *)&ei[e4 * 4];
    int4 d = *(const int4 *)&ei[EE + e4 * 4];
    g_csr[g_rowptr[d.x] + atomicAdd(&g_fill[d.x], 1)] = s.x;
    g_csr[g_rowptr[d.y] + atomicAdd(&g_fill[d.y], 1)] = s.y;
    g_csr[g_rowptr[d.z] + atomicAdd(&g_fill[d.z], 1)] = s.z;
    g_csr[g_rowptr[d.w] + atomicAdd(&g_fill[d.w], 1)] = s.w;
}

// ------------------------- GEMM: Y = ds[i] * (A @ W), W is [Kin,128] -------------------------
// BM=64 BN=128 BK=32, 256 threads, each thread 4 rows x 8 cols via fma.rn.f32x2
__global__ __launch_bounds__(256) void k_gemm(const float *__restrict__ Aext, int useExt,
                                              int whichSrc,
                                              const float *__restrict__ W, int Kin) {
    __shared__ float As[32][68];   // transposed A tile, padded (68*4B row = 16B aligned)
    __shared__ float Bs[32][128];
    const float *A = useExt ? Aext : pickX(whichSrc);
    int tid = threadIdx.x;
    int tx = tid & 15;   // col group
    int ty = tid >> 4;   // row group
    int row0 = blockIdx.x * 64;
    ull acc[4][4];
#pragma unroll
    for (int r = 0; r < 4; ++r)
#pragma unroll
        for (int c = 0; c < 4; ++c) acc[r][c] = 0ull;

    for (int k0 = 0; k0 < Kin; k0 += 32) {
#pragma unroll
        for (int it = 0; it < 2; ++it) {
            int s = tid + it * 256;
            int m = s >> 3, kq = s & 7;
            int row = row0 + m;
            float4 v = make_float4(0.f, 0.f, 0.f, 0.f);
            if (row < NN) v = *(const float4 *)&A[(size_t)row * Kin + k0 + kq * 4];
            As[kq * 4 + 0][m] = v.x; As[kq * 4 + 1][m] = v.y;
            As[kq * 4 + 2][m] = v.z; As[kq * 4 + 3][m] = v.w;
        }
#pragma unroll
        for (int it = 0; it < 4; ++it) {
            int s = tid + it * 256;
            int kk = s >> 5, jq = s & 31;
            *(float4 *)&Bs[kk][jq * 4] = *(const float4 *)&W[(size_t)(k0 + kk) * 128 + jq * 4];
        }
        __syncthreads();
#pragma unroll
        for (int kk = 0; kk < 32; ++kk) {
            float4 a4 = *(const float4 *)&As[kk][ty * 4];
            ull ap0 = pack2(a4.x, a4.x), ap1 = pack2(a4.y, a4.y);
            ull ap2 = pack2(a4.z, a4.z), ap3 = pack2(a4.w, a4.w);
            const ull *bp = (const ull *)&Bs[kk][tx * 8];
            ull b0 = bp[0], b1 = bp[1], b2 = bp[2], b3 = bp[3];
            ffma2(acc[0][0], ap0, b0); ffma2(acc[0][1], ap0, b1); ffma2(acc[0][2], ap0, b2); ffma2(acc[0][3], ap0, b3);
            ffma2(acc[1][0], ap1, b0); ffma2(acc[1][1], ap1, b1); ffma2(acc[1][2], ap1, b2); ffma2(acc[1][3], ap1, b3);
            ffma2(acc[2][0], ap2, b0); ffma2(acc[2][1], ap2, b1); ffma2(acc[2][2], ap2, b2); ffma2(acc[2][3], ap2, b3);
            ffma2(acc[3][0], ap3, b0); ffma2(acc[3][1], ap3, b1); ffma2(acc[3][2], ap3, b2); ffma2(acc[3][3], ap3, b3);
        }
        __syncthreads();
    }
#pragma unroll
    for (int r = 0; r < 4; ++r) {
        int row = row0 + ty * 4 + r;
        if (row >= NN) continue;
        float sc = g_ds[row];
        float o[8];
#pragma unroll
        for (int c = 0; c < 4; ++c) unpack2(acc[r][c], o[2 * c], o[2 * c + 1]);
        float4 v0 = make_float4(o[0] * sc, o[1] * sc, o[2] * sc, o[3] * sc);
        float4 v1 = make_float4(o[4] * sc, o[5] * sc, o[6] * sc, o[7] * sc);
        *(float4 *)&g_y[(size_t)row * 128 + tx * 8]     = v0;
        *(float4 *)&g_y[(size_t)row * 128 + tx * 8 + 4] = v1;
    }
}

// ------------------------- aggregation: out = relu(ds[d]*(sum_nb y + y[d]) + b) -------------------------
__global__ __launch_bounds__(256) void k_agg(const float *__restrict__ bias, int whichDst) {
    int gw = (blockIdx.x * 256 + threadIdx.x) >> 5;
    int lane = threadIdx.x & 31;
    if (gw >= NN) return;
    float *out = (float *)pickX(whichDst);
    int start = g_rowptr[gw], end = g_rowptr[gw + 1];
    int col = lane * 4;
    float4 acc = *(const float4 *)&g_y[(size_t)gw * 128 + col];  // self term
    int e = start;
    // 4-way unrolled gather for MLP
    for (; e + 4 <= end; e += 4) {
        int s0 = g_csr[e], s1 = g_csr[e + 1], s2 = g_csr[e + 2], s3 = g_csr[e + 3];
        float4 v0 = *(const float4 *)&g_y[(size_t)s0 * 128 + col];
        float4 v1 = *(const float4 *)&g_y[(size_t)s1 * 128 + col];
        float4 v2 = *(const float4 *)&g_y[(size_t)s2 * 128 + col];
        float4 v3 = *(const float4 *)&g_y[(size_t)s3 * 128 + col];
        acc.x += (v0.x + v1.x) + (v2.x + v3.x);
        acc.y += (v0.y + v1.y) + (v2.y + v3.y);
        acc.z += (v0.z + v1.z) + (v2.z + v3.z);
        acc.w += (v0.w + v1.w) + (v2.w + v3.w);
    }
    for (; e < end; ++e) {
        int s = g_csr[e];
        float4 v = *(const float4 *)&g_y[(size_t)s * 128 + col];
        acc.x += v.x; acc.y += v.y; acc.z += v.z; acc.w += v.w;
    }
    float sc = g_ds[gw];
    float4 b4 = *(const float4 *)&bias[col];
    float4 o;
    o.x = fmaxf(fmaf(acc.x, sc, b4.x), 0.f);
    o.y = fmaxf(fmaf(acc.y, sc, b4.y), 0.f);
    o.z = fmaxf(fmaf(acc.z, sc, b4.z), 0.f);
    o.w = fmaxf(fmaf(acc.w, sc, b4.w), 0.f);
    *(float4 *)&out[(size_t)gw * 128 + col] = o;
}

// ------------------------- score: ys = ds * (cat . Ws), then GCN-aggregate scalar -------------------------
__global__ __launch_bounds__(256) void k_score_lin(const float *__restrict__ Ws) {
    __shared__ float sW[384];
    int tid = threadIdx.x;
    for (int i = tid; i < 384; i += 256) sW[i] = Ws[i];
    __syncthreads();
    int gw = (blockIdx.x * 256 + tid) >> 5;
    int lane = tid & 31;
    if (gw >= NN) return;
    size_t base = (size_t)gw * 128;
    float s = 0.f;
#pragma unroll
    for (int t = 0; t < 4; ++t) {
        int c = lane + 32 * t;
        s += g_x1[base + c] * sW[c] + g_x2[base + c] * sW[128 + c] + g_x3[base + c] * sW[256 + c];
    }
    for (int o = 16; o; o >>= 1) s += __shfl_down_sync(0xFFFFFFFFu, s, o);
    if (lane == 0) g_ysc[gw] = g_ds[gw] * s;
}
__global__ __launch_bounds__(256) void k_score_agg(const float *__restrict__ bs) {
    int gw = (blockIdx.x * 256 + threadIdx.x) >> 5;
    int lane = threadIdx.x & 31;
    if (gw >= NN) return;
    int start = g_rowptr[gw], end = g_rowptr[gw + 1];
    float s = 0.f;
    for (int e = start + lane; e < end; e += 32) s += g_ysc[g_csr[e]];
    for (int o = 16; o; o >>= 1) s += __shfl_down_sync(0xFFFFFFFFu, s, o);
    if (lane == 0) {
        float tot = s + g_ysc[gw];
        float sc = fmaf(g_ds[gw], tot, bs[0]);
        g_score[gw] = sc;
        g_ukey[gw] = fkey(sc);
    }
}

// ------------------------- radix select (4 passes of 8 bits) -------------------------
__global__ void k_hist(int pass) {
    __shared__ unsigned sh[256];
    int t = threadIdx.x;
    sh[t] = 0u; __syncthreads();
    int i = blockIdx.x * 256 + t;
    if (i < NN) {
        unsigned u = g_ukey[i];
        bool m = (pass == 0) || ((u >> (32 - 8 * pass)) == g_prefix);
        if (m) atomicAdd(&sh[(u >> (24 - 8 * pass)) & 255u], 1u);
    }
    __syncthreads();
    if (sh[t]) atomicAdd(&g_hist[t], sh[t]);
}
__global__ void k_select() {
    __shared__ unsigned h[256];
    int t = threadIdx.x;
    h[t] = g_hist[t];
    g_hist[t] = 0u;  // ready for next pass
    __syncthreads();
    if (t == 0) {
        unsigned kp = g_kprime, c = 0;
        int b;
        for (b = 255; b >= 0; --b) {
            if (c + h[b] >= kp) break;
            c += h[b];
        }
        if (b < 0) b = 0;  // defensive
        g_prefix = (g_prefix << 8) | (unsigned)b;
        g_kprime = kp - c;
    }
}
__global__ void k_ties() {
    int i = blockIdx.x * blockDim.x + threadIdx.x;
    if (i >= NN) return;
    if (g_ukey[i] == g_prefix) {
        int p = atomicAdd(&g_nties, 1);
        g_tieidx[p] = i;
    }
}
__global__ void k_tieresolve() {
    int M = g_nties;
    unsigned R = g_kprime;
    for (int j = threadIdx.x; j < M; j += blockDim.x) {
        int idx = g_tieidx[j];
        unsigned rank = 0;
        for (int l = 0; l < M; ++l) rank += (g_tieidx[l] < idx) ? 1u : 0u;
        if (rank < R) g_tieflag[idx] = 1;  // lower index wins (jax top_k tie-break)
    }
}

// ------------------------- pooling (max + sum over kept nodes, 384 dims) -------------------------
__global__ __launch_bounds__(384) void k_pool() {
    int c = threadIdx.x;  // 0..383
    const float *xa = (c < 128) ? g_x1 : ((c < 256) ? g_x2 : g_x3);
    int cc = c & 127;
    unsigned T = g_prefix;
    float mx = -3.402823466e38f, sm = 0.f;
    for (int i = blockIdx.x; i < NN; i += gridDim.x) {
        unsigned u = g_ukey[i];
        if (u < T) continue;
        if (u == T && !g_tieflag[i]) continue;
        float g = tanhf(g_score[i]);
        float v = xa[(size_t)i * 128 + cc] * g;
        mx = fmaxf(mx, v);
        sm += v;
    }
    atomicMaxF(&g_gmax[c], mx);
    atomicAdd(&g_gsum[c], sm);
}

// ------------------------- final MLP head (single block) -------------------------
__global__ __launch_bounds__(128) void k_mlp(const float *__restrict__ Wl1, const float *__restrict__ bl1,
                                             const float *__restrict__ Wl2, const float *__restrict__ bl2,
                                             const float *__restrict__ Wl3, const float *__restrict__ bl3,
                                             float *__restrict__ out) {
    __shared__ float h[768], h1[128], h2[64], lg[10];
    int t = threadIdx.x;
    for (int c = t; c < 384; c += 128) {
        h[c] = g_gmax[c];
        h[384 + c] = g_gsum[c] * (1.0f / KKEEP);
    }
    __syncthreads();
    float s = bl1[t];
    for (int i = 0; i < 768; ++i) s = fmaf(h[i], Wl1[i * 128 + t], s);
    h1[t] = fmaxf(s, 0.f);
    __syncthreads();
    if (t < 64) {
        float s2 = bl2[t];
        for (int i = 0; i < 128; ++i) s2 = fmaf(h1[i], Wl2[i * 64 + t], s2);
        h2[t] = fmaxf(s2, 0.f);
    }
    __syncthreads();
    if (t < 10) {
        float s3 = bl3[t];
        for (int i = 0; i < 64; ++i) s3 = fmaf(h2[i], Wl3[i * 10 + t], s3);
        lg[t] = s3;
    }
    __syncthreads();
    if (t == 0) {
        float m = lg[0];
        for (int j = 1; j < 10; ++j) m = fmaxf(m, lg[j]);
        float se = 0.f;
        for (int j = 0; j < 10; ++j) se += expf(lg[j] - m);
        float lse = m + logf(se);
        for (int j = 0; j < 10; ++j) out[j] = lg[j] - lse;
    }
}

// ------------------------- launch -------------------------
extern "C" void kernel_launch(void *const *d_in, const int *in_sizes, int n_in,
                              void *d_out, int out_size) {
    const float *x      = (const float *)d_in[0];
    const int   *ei     = (const int *)d_in[1];   // int32 (jax x64 disabled)
    // d_in[2] = batch (unused, single graph)
    const float *W1 = (const float *)d_in[3],  *b1  = (const float *)d_in[4];
    const float *W2 = (const float *)d_in[5],  *b2  = (const float *)d_in[6];
    const float *W3 = (const float *)d_in[7],  *b3  = (const float *)d_in[8];
    const float *Ws = (const float *)d_in[9],  *bs  = (const float *)d_in[10];
    const float *Wl1 = (const float *)d_in[11], *bl1 = (const float *)d_in[12];
    const float *Wl2 = (const float *)d_in[13], *bl2 = (const float *)d_in[14];
    const float *Wl3 = (const float *)d_in[15], *bl3 = (const float *)d_in[16];
    float *out = (float *)d_out;

    const int nblkN = (NN + 255) / 256;
    const int nblkE4 = (EE / 4 + 255) / 256;
    const int nblkW = (NN * 32 + 255) / 256;   // 1 warp per node
    const int nblkG = (NN + 63) / 64;

    // Prologue ordered so the ncu capture slot (4th launch) hits k_gemm layer-1.
    k_init<<<nblkN, 256>>>();
    k_count<<<nblkE4, 256>>>(ei);
    k_node<<<nblkN, 256>>>();
    // GCN layer 1 GEMM (needs only g_ds, not CSR)
    k_gemm<<<nblkG, 256>>>(x, 1, 0, W1, FIN);
    // CSR build
    k_chunksum<<<NCH, 256>>>();
    k_scanchunks<<<1, 1>>>();
    k_scanwrite<<<NCH, 1024>>>();
    k_scatter<<<nblkE4, 256>>>(ei);
    // GCN layer 1 aggregate
    k_agg<<<nblkW, 256>>>(b1, 1);
    // GCN layer 2
    k_gemm<<<nblkG, 256>>>(nullptr, 0, 1, W2, HH);
    k_agg<<<nblkW, 256>>>(b2, 2);
    // GCN layer 3
    k_gemm<<<nblkG, 256>>>(nullptr, 0, 2, W3, HH);
    k_agg<<<nblkW, 256>>>(b3, 3);
    // score GCN (1 channel)
    k_score_lin<<<nblkW, 256>>>(Ws);
    k_score_agg<<<nblkW, 256>>>(bs);
    // exact top-k threshold via 4x8-bit radix select
    for (int p = 0; p < 4; ++p) {
        k_hist<<<nblkN, 256>>>(p);
        k_select<<<1, 256>>>();
    }
    k_ties<<<nblkN, 256>>>();
    k_tieresolve<<<1, 256>>>();
    // gated max/mean readout over kept nodes
    k_pool<<<512, 384>>>();
    // MLP head + log_softmax
    k_mlp<<<1, 128>>>(Wl1, bl1, Wl2, bl2, Wl3, bl3, out);
}

// round 5
// speedup vs baseline: 1.2259x; 1.2259x over previous
#include <cuda_runtime.h>
#include <math.h>
#include <stdint.h>

#define NN 100000
#define EE 1600000
#define FIN 512
#define HH 128
#define KKEEP 50000
#define NCH 98  // ceil(NN/1024)

typedef unsigned long long ull;

// ------------------------- device scratch (globals) -------------------------
__device__ __align__(16) float g_y [(size_t)NN * HH];   // scaled xw buffer (y = ds * X@W)
__device__ __align__(16) float g_x1[(size_t)NN * HH];
__device__ __align__(16) float g_x2[(size_t)NN * HH];
__device__ __align__(16) float g_x3[(size_t)NN * HH];
__device__ float g_ds[NN];
__device__ int   g_degcnt[NN];
__device__ int   g_rowptr[NN + 1];
__device__ int   g_fill[NN];
__device__ int   g_csr[EE];
__device__ int   g_chunksum[NCH];
__device__ int   g_chunkoff[NCH];
__device__ float g_ysc[NN];
__device__ float g_score[NN];
__device__ unsigned g_ukey[NN];
__device__ unsigned g_hist[256];
__device__ unsigned g_prefix;
__device__ unsigned g_kprime;
__device__ int   g_nties;
__device__ int   g_tieidx[NN];
__device__ int   g_tieflag[NN];
__device__ float g_gmax[384];
__device__ float g_gsum[384];

// ------------------------- small helpers -------------------------
__device__ __forceinline__ unsigned fkey(float f) {
    unsigned u = __float_as_uint(f);
    return (u & 0x80000000u) ? ~u : (u | 0x80000000u);
}
__device__ __forceinline__ void atomicMaxF(float *addr, float val) {
    if (val >= 0.f) atomicMax((int *)addr, __float_as_int(val));
    else            atomicMin((unsigned *)addr, __float_as_uint(val));
}
__device__ __forceinline__ const float *pickX(int w) {
    return w == 1 ? g_x1 : (w == 2 ? g_x2 : g_x3);
}
__device__ __forceinline__ uint32_t to_tf32_bits(float x) {
    uint32_t u;
    asm("cvt.rna.tf32.f32 %0, %1;" : "=r"(u) : "f"(x));
    return u;
}
__device__ __forceinline__ void mma1688(float *d, const uint32_t *a, const uint32_t *b) {
    asm volatile("mma.sync.aligned.m16n8k8.row.col.f32.tf32.tf32.f32 "
                 "{%0,%1,%2,%3}, {%4,%5,%6,%7}, {%8,%9}, {%0,%1,%2,%3};"
                 : "+f"(d[0]), "+f"(d[1]), "+f"(d[2]), "+f"(d[3])
                 : "r"(a[0]), "r"(a[1]), "r"(a[2]), "r"(a[3]), "r"(b[0]), "r"(b[1]));
}

// ------------------------- init -------------------------
__global__ void k_init() {
    int i = blockIdx.x * blockDim.x + threadIdx.x;
    if (i < NN) { g_degcnt[i] = 0; g_fill[i] = 0; g_tieflag[i] = 0; }
    if (i < 384) { g_gmax[i] = -3.402823466e38f; g_gsum[i] = 0.f; }
    if (i < 256) g_hist[i] = 0u;
    if (i == 0) { g_prefix = 0u; g_kprime = (unsigned)KKEEP; g_nties = 0; }
}

// ------------------------- degree / CSR build (edge_index is int32) -------------------------
__global__ void k_count(const int *__restrict__ ei) {
    int e4 = blockIdx.x * blockDim.x + threadIdx.x;
    if (e4 >= EE / 4) return;
    int4 d = *(const int4 *)&ei[EE + e4 * 4];
    atomicAdd(&g_degcnt[d.x], 1);
    atomicAdd(&g_degcnt[d.y], 1);
    atomicAdd(&g_degcnt[d.z], 1);
    atomicAdd(&g_degcnt[d.w], 1);
}
__global__ void k_node() {
    int i = blockIdx.x * blockDim.x + threadIdx.x;
    if (i >= NN) return;
    g_ds[i] = rsqrtf((float)(g_degcnt[i] + 1));
}
__global__ void k_chunksum() {
    __shared__ int sm[256];
    int t = threadIdx.x, b = blockIdx.x;
    int s = 0;
    for (int j = t; j < 1024; j += 256) {
        int idx = b * 1024 + j;
        if (idx < NN) s += g_degcnt[idx];
    }
    sm[t] = s; __syncthreads();
    for (int o = 128; o; o >>= 1) { if (t < o) sm[t] += sm[t + o]; __syncthreads(); }
    if (t == 0) g_chunksum[b] = sm[0];
}
__global__ void k_scanchunks() {
    int run = 0;
    for (int c = 0; c < NCH; ++c) { g_chunkoff[c] = run; run += g_chunksum[c]; }
    g_rowptr[NN] = EE;
}
__global__ void k_scanwrite() {
    __shared__ int sd[1024];
    int t = threadIdx.x, b = blockIdx.x;
    int idx = b * 1024 + t;
    int v = (idx < NN) ? g_degcnt[idx] : 0;
    int x = v;
    for (int o = 1; o < 1024; o <<= 1) {
        sd[t] = x; __syncthreads();
        if (t >= o) x += sd[t - o];
        __syncthreads();
    }
    if (idx < NN) g_rowptr[idx] = g_chunkoff[b] + x - v;
}
__global__ void k_scatter(const int *__restrict__ ei) {
    int e4 = blockIdx.x * blockDim.x + threadIdx.x;
    if (e4 >= EE / 4) return;
    int4 s = *(const int4 *)&ei[e4 * 4];
    int4 d = *(const int4 *)&ei[EE + e4 * 4];
    g_csr[g_rowptr[d.x] + atomicAdd(&g_fill[d.x], 1)] = s.x;
    g_csr[g_rowptr[d.y] + atomicAdd(&g_fill[d.y], 1)] = s.y;
    g_csr[g_rowptr[d.z] + atomicAdd(&g_fill[d.z], 1)] = s.z;
    g_csr[g_rowptr[d.w] + atomicAdd(&g_fill[d.w], 1)] = s.w;
}

// ------------------------- GEMM via mma.sync tf32 (3xTF32): Y = ds[i] * (A @ W) ----
// CTA tile 128x128, BK=32, 8 warps each 32x64 (warp grid 4 M x 2 N).
// SMEM holds fragment-major hi/lo copies of A (128x32) and B=W^T (128n x 32k).
//   A frag layout: [mt(8)][ks(4)][lane(32)][4 floats]   (LDS.128 per fragment)
//   B frag layout: [nt(16)][ks(4)][lane(32)][2 floats]  (LDS.64 per fragment)
#define GT_SMEM_BYTES (4 * 16384)
__global__ __launch_bounds__(256, 2) void k_gemm_mma(const float *__restrict__ Aext, int useExt,
                                                     int whichSrc,
                                                     const float *__restrict__ W, int Kin) {
    extern __shared__ char smem[];
    float *a_hi_s = (float *)smem;
    float *a_lo_s = (float *)(smem + 16384);
    float *b_hi_s = (float *)(smem + 32768);
    float *b_lo_s = (float *)(smem + 49152);
    const float *A = useExt ? Aext : pickX(whichSrc);

    int tid = threadIdx.x, wid = tid >> 5, lane = tid & 31;
    int wm = wid & 3, wn = wid >> 2;   // warp coords: 4 in M, 2 in N
    int row0 = blockIdx.x * 128;

    float acc[2][8][4];
#pragma unroll
    for (int mt = 0; mt < 2; ++mt)
#pragma unroll
        for (int nt = 0; nt < 8; ++nt)
#pragma unroll
            for (int q = 0; q < 4; ++q) acc[mt][nt][q] = 0.f;

    int nchunks = Kin >> 5;
    for (int c = 0; c < nchunks; ++c) {
        int k0 = c << 5;
        // ---- stage A tile (128 rows x 32 k) as hi/lo fragments ----
#pragma unroll
        for (int it = 0; it < 4; ++it) {
            int i = tid + it * 256;            // 0..1023 float4 slots
            int m = i >> 3, kq = i & 7;        // kq*4 = k offset
            int row = row0 + m;
            float4 v = make_float4(0.f, 0.f, 0.f, 0.f);
            if (row < NN) v = *(const float4 *)&A[(size_t)row * Kin + k0 + kq * 4];
            int mt = m >> 4, ks = kq >> 1;
            int reg = (kq & 1) * 2 + (((m & 15) >= 8) ? 1 : 0);
            int l0 = (m & 7) * 4;
            int o = ((mt * 4 + ks) * 32 + l0) * 4 + reg;
            uint32_t hx = to_tf32_bits(v.x), hy = to_tf32_bits(v.y);
            uint32_t hz = to_tf32_bits(v.z), hw = to_tf32_bits(v.w);
            a_hi_s[o + 0]  = __uint_as_float(hx);
            a_hi_s[o + 4]  = __uint_as_float(hy);
            a_hi_s[o + 8]  = __uint_as_float(hz);
            a_hi_s[o + 12] = __uint_as_float(hw);
            a_lo_s[o + 0]  = __uint_as_float(to_tf32_bits(v.x - __uint_as_float(hx)));
            a_lo_s[o + 4]  = __uint_as_float(to_tf32_bits(v.y - __uint_as_float(hy)));
            a_lo_s[o + 8]  = __uint_as_float(to_tf32_bits(v.z - __uint_as_float(hz)));
            a_lo_s[o + 12] = __uint_as_float(to_tf32_bits(v.w - __uint_as_float(hw)));
        }
        // ---- stage B tile: B[n][k] = W[k0+k][n], hi/lo fragments ----
#pragma unroll
        for (int it = 0; it < 16; ++it) {
            int i = tid + it * 256;            // 0..4095
            int k = i >> 7, n = i & 127;
            float w = W[(size_t)(k0 + k) * 128 + n];
            uint32_t hb = to_tf32_bits(w);
            float lo = w - __uint_as_float(hb);
            int nt = n >> 3, ks = k >> 3;
            int reg = ((k & 7) >= 4) ? 1 : 0;
            int lb = (n & 7) * 4 + (k & 3);
            int o = ((nt * 4 + ks) * 32 + lb) * 2 + reg;
            b_hi_s[o] = __uint_as_float(hb);
            b_lo_s[o] = __uint_as_float(to_tf32_bits(lo));
        }
        __syncthreads();
        // ---- compute ----
#pragma unroll
        for (int ks = 0; ks < 4; ++ks) {
            uint32_t ah[2][4], al[2][4];
#pragma unroll
            for (int mt = 0; mt < 2; ++mt) {
                int mtg = wm * 2 + mt;
                const uint4 *ph = (const uint4 *)&a_hi_s[((mtg * 4 + ks) * 32 + lane) * 4];
                const uint4 *pl = (const uint4 *)&a_lo_s[((mtg * 4 + ks) * 32 + lane) * 4];
                uint4 vh = *ph, vl = *pl;
                ah[mt][0] = vh.x; ah[mt][1] = vh.y; ah[mt][2] = vh.z; ah[mt][3] = vh.w;
                al[mt][0] = vl.x; al[mt][1] = vl.y; al[mt][2] = vl.z; al[mt][3] = vl.w;
            }
#pragma unroll
            for (int nt = 0; nt < 8; ++nt) {
                int ntg = wn * 8 + nt;
                const uint2 *qh = (const uint2 *)&b_hi_s[((ntg * 4 + ks) * 32 + lane) * 2];
                const uint2 *ql = (const uint2 *)&b_lo_s[((ntg * 4 + ks) * 32 + lane) * 2];
                uint2 vh = *qh, vl = *ql;
                uint32_t bh[2] = {vh.x, vh.y};
                uint32_t bl[2] = {vl.x, vl.y};
#pragma unroll
                for (int mt = 0; mt < 2; ++mt) {
                    mma1688(acc[mt][nt], ah[mt], bh);
                    mma1688(acc[mt][nt], ah[mt], bl);
                    mma1688(acc[mt][nt], al[mt], bh);
                }
            }
        }
        __syncthreads();
    }

    // ---- epilogue: scale by ds[row], store to g_y ----
    int r = lane >> 2;            // 0..7
    int c2 = (lane & 3) * 2;      // 0,2,4,6
#pragma unroll
    for (int mt = 0; mt < 2; ++mt) {
        int rbase = row0 + wm * 32 + mt * 16 + r;
#pragma unroll
        for (int half = 0; half < 2; ++half) {
            int row = rbase + half * 8;
            if (row >= NN) continue;
            float sc = g_ds[row];
            float *dst = &g_y[(size_t)row * 128 + wn * 64 + c2];
#pragma unroll
            for (int nt = 0; nt < 8; ++nt) {
                float2 v;
                v.x = acc[mt][nt][half * 2 + 0] * sc;
                v.y = acc[mt][nt][half * 2 + 1] * sc;
                *(float2 *)(dst + nt * 8) = v;
            }
        }
    }
}

// ------------------------- aggregation: out = relu(ds[d]*(sum_nb y + y[d]) + b) -------------------------
__global__ __launch_bounds__(256) void k_agg(const float *__restrict__ bias, int whichDst) {
    int gw = (blockIdx.x * 256 + threadIdx.x) >> 5;
    int lane = threadIdx.x & 31;
    if (gw >= NN) return;
    float *out = (float *)pickX(whichDst);
    int start = g_rowptr[gw], end = g_rowptr[gw + 1];
    int col = lane * 4;
    float4 acc = *(const float4 *)&g_y[(size_t)gw * 128 + col];  // self term
    int e = start;
    for (; e + 4 <= end; e += 4) {
        int s0 = g_csr[e], s1 = g_csr[e + 1], s2 = g_csr[e + 2], s3 = g_csr[e + 3];
        float4 v0 = *(const float4 *)&g_y[(size_t)s0 * 128 + col];
        float4 v1 = *(const float4 *)&g_y[(size_t)s1 * 128 + col];
        float4 v2 = *(const float4 *)&g_y[(size_t)s2 * 128 + col];
        float4 v3 = *(const float4 *)&g_y[(size_t)s3 * 128 + col];
        acc.x += (v0.x + v1.x) + (v2.x + v3.x);
        acc.y += (v0.y + v1.y) + (v2.y + v3.y);
        acc.z += (v0.z + v1.z) + (v2.z + v3.z);
        acc.w += (v0.w + v1.w) + (v2.w + v3.w);
    }
    for (; e < end; ++e) {
        int s = g_csr[e];
        float4 v = *(const float4 *)&g_y[(size_t)s * 128 + col];
        acc.x += v.x; acc.y += v.y; acc.z += v.z; acc.w += v.w;
    }
    float sc = g_ds[gw];
    float4 b4 = *(const float4 *)&bias[col];
    float4 o;
    o.x = fmaxf(fmaf(acc.x, sc, b4.x), 0.f);
    o.y = fmaxf(fmaf(acc.y, sc, b4.y), 0.f);
    o.z = fmaxf(fmaf(acc.z, sc, b4.z), 0.f);
    o.w = fmaxf(fmaf(acc.w, sc, b4.w), 0.f);
    *(float4 *)&out[(size_t)gw * 128 + col] = o;
}

// ------------------------- score: ys = ds * (cat . Ws), then GCN-aggregate scalar -------------------------
__global__ __launch_bounds__(256) void k_score_lin(const float *__restrict__ Ws) {
    __shared__ float sW[384];
    int tid = threadIdx.x;
    for (int i = tid; i < 384; i += 256) sW[i] = Ws[i];
    __syncthreads();
    int gw = (blockIdx.x * 256 + tid) >> 5;
    int lane = tid & 31;
    if (gw >= NN) return;
    size_t base = (size_t)gw * 128;
    float s = 0.f;
#pragma unroll
    for (int t = 0; t < 4; ++t) {
        int c = lane + 32 * t;
        s += g_x1[base + c] * sW[c] + g_x2[base + c] * sW[128 + c] + g_x3[base + c] * sW[256 + c];
    }
    for (int o = 16; o; o >>= 1) s += __shfl_down_sync(0xFFFFFFFFu, s, o);
    if (lane == 0) g_ysc[gw] = g_ds[gw] * s;
}
__global__ __launch_bounds__(256) void k_score_agg(const float *__restrict__ bs) {
    int gw = (blockIdx.x * 256 + threadIdx.x) >> 5;
    int lane = threadIdx.x & 31;
    if (gw >= NN) return;
    int start = g_rowptr[gw], end = g_rowptr[gw + 1];
    float s = 0.f;
    for (int e = start + lane; e < end; e += 32) s += g_ysc[g_csr[e]];
    for (int o = 16; o; o >>= 1) s += __shfl_down_sync(0xFFFFFFFFu, s, o);
    if (lane == 0) {
        float tot = s + g_ysc[gw];
        float sc = fmaf(g_ds[gw], tot, bs[0]);
        g_score[gw] = sc;
        g_ukey[gw] = fkey(sc);
    }
}

// ------------------------- radix select (4 passes of 8 bits) -------------------------
__global__ void k_hist(int pass) {
    __shared__ unsigned sh[256];
    int t = threadIdx.x;
    sh[t] = 0u; __syncthreads();
    int i = blockIdx.x * 256 + t;
    if (i < NN) {
        unsigned u = g_ukey[i];
        bool m = (pass == 0) || ((u >> (32 - 8 * pass)) == g_prefix);
        if (m) atomicAdd(&sh[(u >> (24 - 8 * pass)) & 255u], 1u);
    }
    __syncthreads();
    if (sh[t]) atomicAdd(&g_hist[t], sh[t]);
}
__global__ void k_select() {
    __shared__ unsigned h[256];
    int t = threadIdx.x;
    h[t] = g_hist[t];
    g_hist[t] = 0u;
    __syncthreads();
    if (t == 0) {
        unsigned kp = g_kprime, c = 0;
        int b;
        for (b = 255; b >= 0; --b) {
            if (c + h[b] >= kp) break;
            c += h[b];
        }
        if (b < 0) b = 0;
        g_prefix = (g_prefix << 8) | (unsigned)b;
        g_kprime = kp - c;
    }
}
__global__ void k_ties() {
    int i = blockIdx.x * blockDim.x + threadIdx.x;
    if (i >= NN) return;
    if (g_ukey[i] == g_prefix) {
        int p = atomicAdd(&g_nties, 1);
        g_tieidx[p] = i;
    }
}
__global__ void k_tieresolve() {
    int M = g_nties;
    unsigned R = g_kprime;
    for (int j = threadIdx.x; j < M; j += blockDim.x) {
        int idx = g_tieidx[j];
        unsigned rank = 0;
        for (int l = 0; l < M; ++l) rank += (g_tieidx[l] < idx) ? 1u : 0u;
        if (rank < R) g_tieflag[idx] = 1;
    }
}

// ------------------------- pooling (max + sum over kept nodes, 384 dims) -------------------------
__global__ __launch_bounds__(384) void k_pool() {
    int c = threadIdx.x;
    const float *xa = (c < 128) ? g_x1 : ((c < 256) ? g_x2 : g_x3);
    int cc = c & 127;
    unsigned T = g_prefix;
    float mx = -3.402823466e38f, sm = 0.f;
    for (int i = blockIdx.x; i < NN; i += gridDim.x) {
        unsigned u = g_ukey[i];
        if (u < T) continue;
        if (u == T && !g_tieflag[i]) continue;
        float g = tanhf(g_score[i]);
        float v = xa[(size_t)i * 128 + cc] * g;
        mx = fmaxf(mx, v);
        sm += v;
    }
    atomicMaxF(&g_gmax[c], mx);
    atomicAdd(&g_gsum[c], sm);
}

// ------------------------- final MLP head (single block) -------------------------
__global__ __launch_bounds__(128) void k_mlp(const float *__restrict__ Wl1, const float *__restrict__ bl1,
                                             const float *__restrict__ Wl2, const float *__restrict__ bl2,
                                             const float *__restrict__ Wl3, const float *__restrict__ bl3,
                                             float *__restrict__ out) {
    __shared__ float h[768], h1[128], h2[64], lg[10];
    int t = threadIdx.x;
    for (int c = t; c < 384; c += 128) {
        h[c] = g_gmax[c];
        h[384 + c] = g_gsum[c] * (1.0f / KKEEP);
    }
    __syncthreads();
    float s = bl1[t];
    for (int i = 0; i < 768; ++i) s = fmaf(h[i], Wl1[i * 128 + t], s);
    h1[t] = fmaxf(s, 0.f);
    __syncthreads();
    if (t < 64) {
        float s2 = bl2[t];
        for (int i = 0; i < 128; ++i) s2 = fmaf(h1[i], Wl2[i * 64 + t], s2);
        h2[t] = fmaxf(s2, 0.f);
    }
    __syncthreads();
    if (t < 10) {
        float s3 = bl3[t];
        for (int i = 0; i < 64; ++i) s3 = fmaf(h2[i], Wl3[i * 10 + t], s3);
        lg[t] = s3;
    }
    __syncthreads();
    if (t == 0) {
        float m = lg[0];
        for (int j = 1; j < 10; ++j) m = fmaxf(m, lg[j]);
        float se = 0.f;
        for (int j = 0; j < 10; ++j) se += expf(lg[j] - m);
        float lse = m + logf(se);
        for (int j = 0; j < 10; ++j) out[j] = lg[j] - lse;
    }
}

// ------------------------- launch -------------------------
extern "C" void kernel_launch(void *const *d_in, const int *in_sizes, int n_in,
                              void *d_out, int out_size) {
    const float *x      = (const float *)d_in[0];
    const int   *ei     = (const int *)d_in[1];   // int32
    const float *W1 = (const float *)d_in[3],  *b1  = (const float *)d_in[4];
    const float *W2 = (const float *)d_in[5],  *b2  = (const float *)d_in[6];
    const float *W3 = (const float *)d_in[7],  *b3  = (const float *)d_in[8];
    const float *Ws = (const float *)d_in[9],  *bs  = (const float *)d_in[10];
    const float *Wl1 = (const float *)d_in[11], *bl1 = (const float *)d_in[12];
    const float *Wl2 = (const float *)d_in[13], *bl2 = (const float *)d_in[14];
    const float *Wl3 = (const float *)d_in[15], *bl3 = (const float *)d_in[16];
    float *out = (float *)d_out;

    const int nblkN = (NN + 255) / 256;
    const int nblkE4 = (EE / 4 + 255) / 256;
    const int nblkW = (NN * 32 + 255) / 256;
    const int nblkT = (NN + 127) / 128;   // gemm blocks (128 rows each)

    cudaFuncSetAttribute(k_gemm_mma, cudaFuncAttributeMaxDynamicSharedMemorySize, GT_SMEM_BYTES);

    // Prologue ordered so the ncu capture slot (4th launch) hits layer-1 gemm.
    k_init<<<nblkN, 256>>>();
    k_count<<<nblkE4, 256>>>(ei);
    k_node<<<nblkN, 256>>>();
    // GCN layer 1 GEMM (needs only g_ds, not CSR)
    k_gemm_mma<<<nblkT, 256, GT_SMEM_BYTES>>>(x, 1, 0, W1, FIN);
    // CSR build
    k_chunksum<<<NCH, 256>>>();
    k_scanchunks<<<1, 1>>>();
    k_scanwrite<<<NCH, 1024>>>();
    k_scatter<<<nblkE4, 256>>>(ei);
    // GCN layer 1 aggregate
    k_agg<<<nblkW, 256>>>(b1, 1);
    // GCN layer 2
    k_gemm_mma<<<nblkT, 256, GT_SMEM_BYTES>>>(nullptr, 0, 1, W2, HH);
    k_agg<<<nblkW, 256>>>(b2, 2);
    // GCN layer 3
    k_gemm_mma<<<nblkT, 256, GT_SMEM_BYTES>>>(nullptr, 0, 2, W3, HH);
    k_agg<<<nblkW, 256>>>(b3, 3);
    // score GCN (1 channel)
    k_score_lin<<<nblkW, 256>>>(Ws);
    k_score_agg<<<nblkW, 256>>>(bs);
    // exact top-k threshold via 4x8-bit radix select
    for (int p = 0; p < 4; ++p) {
        k_hist<<<nblkN, 256>>>(p);
        k_select<<<1, 256>>>();
    }
    k_ties<<<nblkN, 256>>>();
    k_tieresolve<<<1, 256>>>();
    // gated max/mean readout over kept nodes
    k_pool<<<512, 384>>>();
    // MLP head + log_softmax
    k_mlp<<<1, 128>>>(Wl1, bl1, Wl2, bl2, Wl3, bl3, out);
}

// round 6
// speedup vs baseline: 1.2667x; 1.0333x over previous
#include <cuda_runtime.h>
#include <math.h>
#include <stdint.h>

#define NN 100000
#define EE 1600000
#define FIN 512
#define HH 128
#define KKEEP 50000
#define NCH 98  // ceil(NN/1024)

typedef unsigned long long ull;

// ------------------------- device scratch (globals) -------------------------
__device__ __align__(16) float g_y [(size_t)NN * HH];   // scaled xw buffer (y = ds * X@W)
__device__ __align__(16) float g_x1[(size_t)NN * HH];
__device__ __align__(16) float g_x2[(size_t)NN * HH];
__device__ __align__(16) float g_x3[(size_t)NN * HH];
__device__ float g_ds[NN];
__device__ int   g_degcnt[NN];
__device__ int   g_rowptr[NN + 1];
__device__ int   g_fill[NN];
__device__ int   g_csr[EE];
__device__ int   g_chunksum[NCH];
__device__ int   g_chunkoff[NCH];
__device__ float g_ysc[NN];
__device__ float g_score[NN];
__device__ unsigned g_ukey[NN];
__device__ unsigned g_hist[256];
__device__ unsigned g_prefix;
__device__ unsigned g_kprime;
__device__ int   g_nties;
__device__ int   g_tieidx[NN];
__device__ int   g_tieflag[NN];
__device__ float g_gmax[384];
__device__ float g_gsum[384];

// ------------------------- small helpers -------------------------
__device__ __forceinline__ unsigned fkey(float f) {
    unsigned u = __float_as_uint(f);
    return (u & 0x80000000u) ? ~u : (u | 0x80000000u);
}
__device__ __forceinline__ void atomicMaxF(float *addr, float val) {
    if (val >= 0.f) atomicMax((int *)addr, __float_as_int(val));
    else            atomicMin((unsigned *)addr, __float_as_uint(val));
}
__device__ __forceinline__ const float *pickX(int w) {
    return w == 1 ? g_x1 : (w == 2 ? g_x2 : g_x3);
}
__device__ __forceinline__ uint32_t to_tf32_bits(float x) {
    uint32_t u;
    asm("cvt.rna.tf32.f32 %0, %1;" : "=r"(u) : "f"(x));
    return u;
}
__device__ __forceinline__ void split_tf32(float a, uint32_t &hi, uint32_t &lo) {
    hi = to_tf32_bits(a);
    lo = to_tf32_bits(a - __uint_as_float(hi));
}
__device__ __forceinline__ void mma1688(float *d, const uint32_t *a, const uint32_t *b) {
    asm volatile("mma.sync.aligned.m16n8k8.row.col.f32.tf32.tf32.f32 "
                 "{%0,%1,%2,%3}, {%4,%5,%6,%7}, {%8,%9}, {%0,%1,%2,%3};"
                 : "+f"(d[0]), "+f"(d[1]), "+f"(d[2]), "+f"(d[3])
                 : "r"(a[0]), "r"(a[1]), "r"(a[2]), "r"(a[3]), "r"(b[0]), "r"(b[1]));
}

// ------------------------- init -------------------------
__global__ void k_init() {
    int i = blockIdx.x * blockDim.x + threadIdx.x;
    if (i < NN) { g_degcnt[i] = 0; g_fill[i] = 0; g_tieflag[i] = 0; }
    if (i < 384) { g_gmax[i] = -3.402823466e38f; g_gsum[i] = 0.f; }
    if (i < 256) g_hist[i] = 0u;
    if (i == 0) { g_prefix = 0u; g_kprime = (unsigned)KKEEP; g_nties = 0; }
}

// ------------------------- degree / CSR build (edge_index is int32) -------------------------
__global__ void k_count(const int *__restrict__ ei) {
    int e4 = blockIdx.x * blockDim.x + threadIdx.x;
    if (e4 >= EE / 4) return;
    int4 d = *(const int4 *)&ei[EE + e4 * 4];
    atomicAdd(&g_degcnt[d.x], 1);
    atomicAdd(&g_degcnt[d.y], 1);
    atomicAdd(&g_degcnt[d.z], 1);
    atomicAdd(&g_degcnt[d.w], 1);
}
__global__ void k_node() {
    int i = blockIdx.x * blockDim.x + threadIdx.x;
    if (i >= NN) return;
    g_ds[i] = rsqrtf((float)(g_degcnt[i] + 1));
}
__global__ void k_chunksum() {
    __shared__ int sm[256];
    int t = threadIdx.x, b = blockIdx.x;
    int s = 0;
    for (int j = t; j < 1024; j += 256) {
        int idx = b * 1024 + j;
        if (idx < NN) s += g_degcnt[idx];
    }
    sm[t] = s; __syncthreads();
    for (int o = 128; o; o >>= 1) { if (t < o) sm[t] += sm[t + o]; __syncthreads(); }
    if (t == 0) g_chunksum[b] = sm[0];
}
__global__ void k_scanchunks() {
    int run = 0;
    for (int c = 0; c < NCH; ++c) { g_chunkoff[c] = run; run += g_chunksum[c]; }
    g_rowptr[NN] = EE;
}
__global__ void k_scanwrite() {
    __shared__ int sd[1024];
    int t = threadIdx.x, b = blockIdx.x;
    int idx = b * 1024 + t;
    int v = (idx < NN) ? g_degcnt[idx] : 0;
    int x = v;
    for (int o = 1; o < 1024; o <<= 1) {
        sd[t] = x; __syncthreads();
        if (t >= o) x += sd[t - o];
        __syncthreads();
    }
    if (idx < NN) g_rowptr[idx] = g_chunkoff[b] + x - v;
}
__global__ void k_scatter(const int *__restrict__ ei) {
    int e4 = blockIdx.x * blockDim.x + threadIdx.x;
    if (e4 >= EE / 4) return;
    int4 s = *(const int4 *)&ei[e4 * 4];
    int4 d = *(const int4 *)&ei[EE + e4 * 4];
    g_csr[g_rowptr[d.x] + atomicAdd(&g_fill[d.x], 1)] = s.x;
    g_csr[g_rowptr[d.y] + atomicAdd(&g_fill[d.y], 1)] = s.y;
    g_csr[g_rowptr[d.z] + atomicAdd(&g_fill[d.z], 1)] = s.z;
    g_csr[g_rowptr[d.w] + atomicAdd(&g_fill[d.w], 1)] = s.w;
}

// ------------------------- GEMM via mma.sync tf32 (3xTF32): Y = ds[i] * (A @ W) ----
// CTA tile 128x128, BK=32, 8 warps each 32x64 (warp grid 4 M x 2 N).
// Single f32 copy in SMEM, fragment-major; hi/lo tf32 split computed in registers.
//   A frag layout: [mt(8)][ks(4)][lane(32)][4 floats]   (LDS.128 per fragment)
//   B frag layout: [nt(16)][ks(4)][lane(32)][2 floats]  (LDS.64 per fragment)
#define GT_SMEM_BYTES (2 * 16384)
__global__ __launch_bounds__(256, 2) void k_gemm_mma(const float *__restrict__ Aext, int useExt,
                                                     int whichSrc,
                                                     const float *__restrict__ W, int Kin) {
    extern __shared__ char smem[];
    float *a_s = (float *)smem;
    float *b_s = (float *)(smem + 16384);
    const float *A = useExt ? Aext : pickX(whichSrc);

    int tid = threadIdx.x, wid = tid >> 5, lane = tid & 31;
    int wm = wid & 3, wn = wid >> 2;   // warp coords: 4 in M, 2 in N
    int row0 = blockIdx.x * 128;

    float acc[2][8][4];
#pragma unroll
    for (int mt = 0; mt < 2; ++mt)
#pragma unroll
        for (int nt = 0; nt < 8; ++nt)
#pragma unroll
            for (int q = 0; q < 4; ++q) acc[mt][nt][q] = 0.f;

    int nchunks = Kin >> 5;
    for (int c = 0; c < nchunks; ++c) {
        int k0 = c << 5;
        // ---- stage A tile (128 rows x 32 k), f32, fragment-major ----
#pragma unroll
        for (int it = 0; it < 4; ++it) {
            int i = tid + it * 256;            // 0..1023 float4 slots
            int m = i >> 3, kq = i & 7;        // kq*4 = k offset
            int row = row0 + m;
            float4 v = make_float4(0.f, 0.f, 0.f, 0.f);
            if (row < NN) v = *(const float4 *)&A[(size_t)row * Kin + k0 + kq * 4];
            int mt = m >> 4, ks = kq >> 1;
            int reg = (kq & 1) * 2 + (((m & 15) >= 8) ? 1 : 0);
            int l0 = (m & 7) * 4;
            int o = ((mt * 4 + ks) * 32 + l0) * 4 + reg;
            a_s[o + 0]  = v.x;
            a_s[o + 4]  = v.y;
            a_s[o + 8]  = v.z;
            a_s[o + 12] = v.w;
        }
        // ---- stage B tile: B[n][k] = W[k0+k][n], f32, fragment-major ----
#pragma unroll
        for (int it = 0; it < 16; ++it) {
            int i = tid + it * 256;            // 0..4095
            int k = i >> 7, n = i & 127;
            float w = W[(size_t)(k0 + k) * 128 + n];
            int nt = n >> 3, ks = k >> 3;
            int reg = ((k & 7) >= 4) ? 1 : 0;
            int lb = (n & 7) * 4 + (k & 3);
            int o = ((nt * 4 + ks) * 32 + lb) * 2 + reg;
            b_s[o] = w;
        }
        __syncthreads();
        // ---- compute ----
#pragma unroll
        for (int ks = 0; ks < 4; ++ks) {
            uint32_t ah[2][4], al[2][4];
#pragma unroll
            for (int mt = 0; mt < 2; ++mt) {
                int mtg = wm * 2 + mt;
                float4 v = *(const float4 *)&a_s[((mtg * 4 + ks) * 32 + lane) * 4];
                split_tf32(v.x, ah[mt][0], al[mt][0]);
                split_tf32(v.y, ah[mt][1], al[mt][1]);
                split_tf32(v.z, ah[mt][2], al[mt][2]);
                split_tf32(v.w, ah[mt][3], al[mt][3]);
            }
#pragma unroll
            for (int nt = 0; nt < 8; ++nt) {
                int ntg = wn * 8 + nt;
                float2 v = *(const float2 *)&b_s[((ntg * 4 + ks) * 32 + lane) * 2];
                uint32_t bh[2], bl[2];
                split_tf32(v.x, bh[0], bl[0]);
                split_tf32(v.y, bh[1], bl[1]);
#pragma unroll
                for (int mt = 0; mt < 2; ++mt) {
                    mma1688(acc[mt][nt], ah[mt], bh);
                    mma1688(acc[mt][nt], ah[mt], bl);
                    mma1688(acc[mt][nt], al[mt], bh);
                }
            }
        }
        __syncthreads();
    }

    // ---- epilogue: scale by ds[row], store to g_y ----
    int r = lane >> 2;            // 0..7
    int c2 = (lane & 3) * 2;      // 0,2,4,6
#pragma unroll
    for (int mt = 0; mt < 2; ++mt) {
        int rbase = row0 + wm * 32 + mt * 16 + r;
#pragma unroll
        for (int half = 0; half < 2; ++half) {
            int row = rbase + half * 8;
            if (row >= NN) continue;
            float sc = g_ds[row];
            float *dst = &g_y[(size_t)row * 128 + wn * 64 + c2];
#pragma unroll
            for (int nt = 0; nt < 8; ++nt) {
                float2 v;
                v.x = acc[mt][nt][half * 2 + 0] * sc;
                v.y = acc[mt][nt][half * 2 + 1] * sc;
                *(float2 *)(dst + nt * 8) = v;
            }
        }
    }
}

// ------------------------- aggregation: out = relu(ds[d]*(sum_nb y + y[d]) + b) -------------------------
__global__ __launch_bounds__(256) void k_agg(const float *__restrict__ bias, int whichDst) {
    int gw = (blockIdx.x * 256 + threadIdx.x) >> 5;
    int lane = threadIdx.x & 31;
    if (gw >= NN) return;
    float *out = (float *)pickX(whichDst);
    int start = g_rowptr[gw], end = g_rowptr[gw + 1];
    int col = lane * 4;
    float4 acc = *(const float4 *)&g_y[(size_t)gw * 128 + col];  // self term
    int e = start;
    for (; e + 4 <= end; e += 4) {
        int s0 = g_csr[e], s1 = g_csr[e + 1], s2 = g_csr[e + 2], s3 = g_csr[e + 3];
        float4 v0 = *(const float4 *)&g_y[(size_t)s0 * 128 + col];
        float4 v1 = *(const float4 *)&g_y[(size_t)s1 * 128 + col];
        float4 v2 = *(const float4 *)&g_y[(size_t)s2 * 128 + col];
        float4 v3 = *(const float4 *)&g_y[(size_t)s3 * 128 + col];
        acc.x += (v0.x + v1.x) + (v2.x + v3.x);
        acc.y += (v0.y + v1.y) + (v2.y + v3.y);
        acc.z += (v0.z + v1.z) + (v2.z + v3.z);
        acc.w += (v0.w + v1.w) + (v2.w + v3.w);
    }
    for (; e < end; ++e) {
        int s = g_csr[e];
        float4 v = *(const float4 *)&g_y[(size_t)s * 128 + col];
        acc.x += v.x; acc.y += v.y; acc.z += v.z; acc.w += v.w;
    }
    float sc = g_ds[gw];
    float4 b4 = *(const float4 *)&bias[col];
    float4 o;
    o.x = fmaxf(fmaf(acc.x, sc, b4.x), 0.f);
    o.y = fmaxf(fmaf(acc.y, sc, b4.y), 0.f);
    o.z = fmaxf(fmaf(acc.z, sc, b4.z), 0.f);
    o.w = fmaxf(fmaf(acc.w, sc, b4.w), 0.f);
    *(float4 *)&out[(size_t)gw * 128 + col] = o;
}

// ------------------------- score: ys = ds * (cat . Ws), then GCN-aggregate scalar -------------------------
__global__ __launch_bounds__(256) void k_score_lin(const float *__restrict__ Ws) {
    __shared__ float sW[384];
    int tid = threadIdx.x;
    for (int i = tid; i < 384; i += 256) sW[i] = Ws[i];
    __syncthreads();
    int gw = (blockIdx.x * 256 + tid) >> 5;
    int lane = tid & 31;
    if (gw >= NN) return;
    size_t base = (size_t)gw * 128;
    float s = 0.f;
#pragma unroll
    for (int t = 0; t < 4; ++t) {
        int c = lane + 32 * t;
        s += g_x1[base + c] * sW[c] + g_x2[base + c] * sW[128 + c] + g_x3[base + c] * sW[256 + c];
    }
    for (int o = 16; o; o >>= 1) s += __shfl_down_sync(0xFFFFFFFFu, s, o);
    if (lane == 0) g_ysc[gw] = g_ds[gw] * s;
}
__global__ __launch_bounds__(256) void k_score_agg(const float *__restrict__ bs) {
    int gw = (blockIdx.x * 256 + threadIdx.x) >> 5;
    int lane = threadIdx.x & 31;
    if (gw >= NN) return;
    int start = g_rowptr[gw], end = g_rowptr[gw + 1];
    float s = 0.f;
    for (int e = start + lane; e < end; e += 32) s += g_ysc[g_csr[e]];
    for (int o = 16; o; o >>= 1) s += __shfl_down_sync(0xFFFFFFFFu, s, o);
    if (lane == 0) {
        float tot = s + g_ysc[gw];
        float sc = fmaf(g_ds[gw], tot, bs[0]);
        g_score[gw] = sc;
        g_ukey[gw] = fkey(sc);
    }
}

// ------------------------- radix select (4 passes of 8 bits) -------------------------
__global__ void k_hist(int pass) {
    __shared__ unsigned sh[256];
    int t = threadIdx.x;
    sh[t] = 0u; __syncthreads();
    int i = blockIdx.x * 256 + t;
    if (i < NN) {
        unsigned u = g_ukey[i];
        bool m = (pass == 0) || ((u >> (32 - 8 * pass)) == g_prefix);
        if (m) atomicAdd(&sh[(u >> (24 - 8 * pass)) & 255u], 1u);
    }
    __syncthreads();
    if (sh[t]) atomicAdd(&g_hist[t], sh[t]);
}
__global__ void k_select() {
    __shared__ unsigned h[256];
    int t = threadIdx.x;
    h[t] = g_hist[t];
    g_hist[t] = 0u;
    __syncthreads();
    if (t == 0) {
        unsigned kp = g_kprime, c = 0;
        int b;
        for (b = 255; b >= 0; --b) {
            if (c + h[b] >= kp) break;
            c += h[b];
        }
        if (b < 0) b = 0;
        g_prefix = (g_prefix << 8) | (unsigned)b;
        g_kprime = kp - c;
    }
}
__global__ void k_ties() {
    int i = blockIdx.x * blockDim.x + threadIdx.x;
    if (i >= NN) return;
    if (g_ukey[i] == g_prefix) {
        int p = atomicAdd(&g_nties, 1);
        g_tieidx[p] = i;
    }
}
__global__ void k_tieresolve() {
    int M = g_nties;
    unsigned R = g_kprime;
    for (int j = threadIdx.x; j < M; j += blockDim.x) {
        int idx = g_tieidx[j];
        unsigned rank = 0;
        for (int l = 0; l < M; ++l) rank += (g_tieidx[l] < idx) ? 1u : 0u;
        if (rank < R) g_tieflag[idx] = 1;
    }
}

// ------------------------- pooling (max + sum over kept nodes, 384 dims) -------------------------
__global__ __launch_bounds__(384) void k_pool() {
    int c = threadIdx.x;
    const float *xa = (c < 128) ? g_x1 : ((c < 256) ? g_x2 : g_x3);
    int cc = c & 127;
    unsigned T = g_prefix;
    float mx = -3.402823466e38f, sm = 0.f;
    for (int i = blockIdx.x; i < NN; i += gridDim.x) {
        unsigned u = g_ukey[i];
        if (u < T) continue;
        if (u == T && !g_tieflag[i]) continue;
        float g = tanhf(g_score[i]);
        float v = xa[(size_t)i * 128 + cc] * g;
        mx = fmaxf(mx, v);
        sm += v;
    }
    atomicMaxF(&g_gmax[c], mx);
    atomicAdd(&g_gsum[c], sm);
}

// ------------------------- final MLP head (single block) -------------------------
__global__ __launch_bounds__(128) void k_mlp(const float *__restrict__ Wl1, const float *__restrict__ bl1,
                                             const float *__restrict__ Wl2, const float *__restrict__ bl2,
                                             const float *__restrict__ Wl3, const float *__restrict__ bl3,
                                             float *__restrict__ out) {
    __shared__ float h[768], h1[128], h2[64], lg[10];
    int t = threadIdx.x;
    for (int c = t; c < 384; c += 128) {
        h[c] = g_gmax[c];
        h[384 + c] = g_gsum[c] * (1.0f / KKEEP);
    }
    __syncthreads();
    float s = bl1[t];
    for (int i = 0; i < 768; ++i) s = fmaf(h[i], Wl1[i * 128 + t], s);
    h1[t] = fmaxf(s, 0.f);
    __syncthreads();
    if (t < 64) {
        float s2 = bl2[t];
        for (int i = 0; i < 128; ++i) s2 = fmaf(h1[i], Wl2[i * 64 + t], s2);
        h2[t] = fmaxf(s2, 0.f);
    }
    __syncthreads();
    if (t < 10) {
        float s3 = bl3[t];
        for (int i = 0; i < 64; ++i) s3 = fmaf(h2[i], Wl3[i * 10 + t], s3);
        lg[t] = s3;
    }
    __syncthreads();
    if (t == 0) {
        float m = lg[0];
        for (int j = 1; j < 10; ++j) m = fmaxf(m, lg[j]);
        float se = 0.f;
        for (int j = 0; j < 10; ++j) se += expf(lg[j] - m);
        float lse = m + logf(se);
        for (int j = 0; j < 10; ++j) out[j] = lg[j] - lse;
    }
}

// ------------------------- launch -------------------------
extern "C" void kernel_launch(void *const *d_in, const int *in_sizes, int n_in,
                              void *d_out, int out_size) {
    const float *x      = (const float *)d_in[0];
    const int   *ei     = (const int *)d_in[1];   // int32
    const float *W1 = (const float *)d_in[3],  *b1  = (const float *)d_in[4];
    const float *W2 = (const float *)d_in[5],  *b2  = (const float *)d_in[6];
    const float *W3 = (const float *)d_in[7],  *b3  = (const float *)d_in[8];
    const float *Ws = (const float *)d_in[9],  *bs  = (const float *)d_in[10];
    const float *Wl1 = (const float *)d_in[11], *bl1 = (const float *)d_in[12];
    const float *Wl2 = (const float *)d_in[13], *bl2 = (const float *)d_in[14];
    const float *Wl3 = (const float *)d_in[15], *bl3 = (const float *)d_in[16];
    float *out = (float *)d_out;

    const int nblkN = (NN + 255) / 256;
    const int nblkE4 = (EE / 4 + 255) / 256;
    const int nblkW = (NN * 32 + 255) / 256;
    const int nblkT = (NN + 127) / 128;   // gemm blocks (128 rows each)

    cudaFuncSetAttribute(k_gemm_mma, cudaFuncAttributeMaxDynamicSharedMemorySize, GT_SMEM_BYTES);

    // Prologue ordered so the ncu capture slot (4th launch) hits layer-1 gemm.
    k_init<<<nblkN, 256>>>();
    k_count<<<nblkE4, 256>>>(ei);
    k_node<<<nblkN, 256>>>();
    // GCN layer 1 GEMM (needs only g_ds, not CSR)
    k_gemm_mma<<<nblkT, 256, GT_SMEM_BYTES>>>(x, 1, 0, W1, FIN);
    // CSR build
    k_chunksum<<<NCH, 256>>>();
    k_scanchunks<<<1, 1>>>();
    k_scanwrite<<<NCH, 1024>>>();
    k_scatter<<<nblkE4, 256>>>(ei);
    // GCN layer 1 aggregate
    k_agg<<<nblkW, 256>>>(b1, 1);
    // GCN layer 2
    k_gemm_mma<<<nblkT, 256, GT_SMEM_BYTES>>>(nullptr, 0, 1, W2, HH);
    k_agg<<<nblkW, 256>>>(b2, 2);
    // GCN layer 3
    k_gemm_mma<<<nblkT, 256, GT_SMEM_BYTES>>>(nullptr, 0, 2, W3, HH);
    k_agg<<<nblkW, 256>>>(b3, 3);
    // score GCN (1 channel)
    k_score_lin<<<nblkW, 256>>>(Ws);
    k_score_agg<<<nblkW, 256>>>(bs);
    // exact top-k threshold via 4x8-bit radix select
    for (int p = 0; p < 4; ++p) {
        k_hist<<<nblkN, 256>>>(p);
        k_select<<<1, 256>>>();
    }
    k_ties<<<nblkN, 256>>>();
    k_tieresolve<<<1, 256>>>();
    // gated max/mean readout over kept nodes
    k_pool<<<512, 384>>>();
    // MLP head + log_softmax
    k_mlp<<<1, 128>>>(Wl1, bl1, Wl2, bl2, Wl3, bl3, out);
}

// round 7
// speedup vs baseline: 1.6947x; 1.3379x over previous
#include <cuda_runtime.h>
#include <math.h>
#include <stdint.h>

#define NN 100000
#define EE 1600000
#define FIN 512
#define HH 128
#define KKEEP 50000
#define NCH 98  // ceil(NN/1024)

typedef unsigned long long ull;

// ------------------------- device scratch (globals) -------------------------
__device__ __align__(16) float g_y [(size_t)NN * HH];   // scaled xw buffer (y = ds * X@W)
__device__ __align__(16) float g_x1[(size_t)NN * HH];
__device__ __align__(16) float g_x2[(size_t)NN * HH];
__device__ __align__(16) float g_x3[(size_t)NN * HH];
__device__ float g_ds[NN];
__device__ int   g_degcnt[NN];
__device__ int   g_rowptr[NN + 1];
__device__ int   g_fill[NN];
__device__ int   g_csr[EE];
__device__ int   g_chunksum[NCH];
__device__ int   g_chunkoff[NCH];
__device__ float g_ysc[NN];
__device__ float g_score[NN];
__device__ unsigned g_ukey[NN];
__device__ unsigned g_hist[256];
__device__ unsigned g_prefix;
__device__ unsigned g_kprime;
__device__ int   g_nties;
__device__ int   g_tieidx[NN];
__device__ int   g_tieflag[NN];
__device__ float g_gmax[384];
__device__ float g_gsum[384];

// ------------------------- small helpers -------------------------
__device__ __forceinline__ unsigned fkey(float f) {
    unsigned u = __float_as_uint(f);
    return (u & 0x80000000u) ? ~u : (u | 0x80000000u);
}
__device__ __forceinline__ void atomicMaxF(float *addr, float val) {
    if (val >= 0.f) atomicMax((int *)addr, __float_as_int(val));
    else            atomicMin((unsigned *)addr, __float_as_uint(val));
}
__device__ __forceinline__ const float *pickX(int w) {
    return w == 1 ? g_x1 : (w == 2 ? g_x2 : g_x3);
}
// pack two f32 into bf16x2 (x -> low half, y -> high half), round-to-nearest
__device__ __forceinline__ uint32_t pack_bf16x2(float x, float y) {
    uint32_t r;
    asm("cvt.rn.bf16x2.f32 %0, %1, %2;" : "=r"(r) : "f"(y), "f"(x));
    return r;
}
// exact f32 value of the bf16 halves
__device__ __forceinline__ float bf16lo_f(uint32_t p) { return __uint_as_float(p << 16); }
__device__ __forceinline__ float bf16hi_f(uint32_t p) { return __uint_as_float(p & 0xFFFF0000u); }
// split pair (x,y) -> hi bf16x2 and lo bf16x2 (lo = rn(x - hi(x)))
__device__ __forceinline__ void split2_bf16(float x, float y, uint32_t &hi, uint32_t &lo) {
    hi = pack_bf16x2(x, y);
    lo = pack_bf16x2(x - bf16lo_f(hi), y - bf16hi_f(hi));
}
__device__ __forceinline__ void mma16816(float *d, const uint32_t *a, const uint32_t *b) {
    asm volatile("mma.sync.aligned.m16n8k16.row.col.f32.bf16.bf16.f32 "
                 "{%0,%1,%2,%3}, {%4,%5,%6,%7}, {%8,%9}, {%0,%1,%2,%3};"
                 : "+f"(d[0]), "+f"(d[1]), "+f"(d[2]), "+f"(d[3])
                 : "r"(a[0]), "r"(a[1]), "r"(a[2]), "r"(a[3]), "r"(b[0]), "r"(b[1]));
}

// ------------------------- init -------------------------
__global__ void k_init() {
    int i = blockIdx.x * blockDim.x + threadIdx.x;
    if (i < NN) { g_degcnt[i] = 0; g_fill[i] = 0; g_tieflag[i] = 0; }
    if (i < 384) { g_gmax[i] = -3.402823466e38f; g_gsum[i] = 0.f; }
    if (i < 256) g_hist[i] = 0u;
    if (i == 0) { g_prefix = 0u; g_kprime = (unsigned)KKEEP; g_nties = 0; }
}

// ------------------------- degree / CSR build (edge_index is int32) -------------------------
__global__ void k_count(const int *__restrict__ ei) {
    int e4 = blockIdx.x * blockDim.x + threadIdx.x;
    if (e4 >= EE / 4) return;
    int4 d = *(const int4 *)&ei[EE + e4 * 4];
    atomicAdd(&g_degcnt[d.x], 1);
    atomicAdd(&g_degcnt[d.y], 1);
    atomicAdd(&g_degcnt[d.z], 1);
    atomicAdd(&g_degcnt[d.w], 1);
}
__global__ void k_node() {
    int i = blockIdx.x * blockDim.x + threadIdx.x;
    if (i >= NN) return;
    g_ds[i] = rsqrtf((float)(g_degcnt[i] + 1));
}
__global__ void k_chunksum() {
    __shared__ int sm[256];
    int t = threadIdx.x, b = blockIdx.x;
    int s = 0;
    for (int j = t; j < 1024; j += 256) {
        int idx = b * 1024 + j;
        if (idx < NN) s += g_degcnt[idx];
    }
    sm[t] = s; __syncthreads();
    for (int o = 128; o; o >>= 1) { if (t < o) sm[t] += sm[t + o]; __syncthreads(); }
    if (t == 0) g_chunksum[b] = sm[0];
}
__global__ void k_scanchunks() {
    int run = 0;
    for (int c = 0; c < NCH; ++c) { g_chunkoff[c] = run; run += g_chunksum[c]; }
    g_rowptr[NN] = EE;
}
__global__ void k_scanwrite() {
    __shared__ int sd[1024];
    int t = threadIdx.x, b = blockIdx.x;
    int idx = b * 1024 + t;
    int v = (idx < NN) ? g_degcnt[idx] : 0;
    int x = v;
    for (int o = 1; o < 1024; o <<= 1) {
        sd[t] = x; __syncthreads();
        if (t >= o) x += sd[t - o];
        __syncthreads();
    }
    if (idx < NN) g_rowptr[idx] = g_chunkoff[b] + x - v;
}
__global__ void k_scatter(const int *__restrict__ ei) {
    int e4 = blockIdx.x * blockDim.x + threadIdx.x;
    if (e4 >= EE / 4) return;
    int4 s = *(const int4 *)&ei[e4 * 4];
    int4 d = *(const int4 *)&ei[EE + e4 * 4];
    g_csr[g_rowptr[d.x] + atomicAdd(&g_fill[d.x], 1)] = s.x;
    g_csr[g_rowptr[d.y] + atomicAdd(&g_fill[d.y], 1)] = s.y;
    g_csr[g_rowptr[d.z] + atomicAdd(&g_fill[d.z], 1)] = s.z;
    g_csr[g_rowptr[d.w] + atomicAdd(&g_fill[d.w], 1)] = s.w;
}

// ------------------------- GEMM via mma.sync bf16 (3-term split): Y = ds[i] * (A @ W) ----
// CTA tile 128x128, BK=32 (2 k16 steps), 8 warps each 32x64 (warp grid 4M x 2N).
// hi/lo bf16 fragments pre-split at staging into SMEM (fragment-major):
//   A: [mt(8)][ks(2)][lane(32)][4 u32]  -> LDS.128 per fragment (8KB each for hi/lo)
//   B: [nt(16)][ks(2)][lane(32)][2 u32] -> LDS.64 per fragment  (8KB each for hi/lo)
#define GT_SMEM_BYTES (4 * 8192)
__global__ __launch_bounds__(256, 2) void k_gemm_mma(const float *__restrict__ Aext, int useExt,
                                                     int whichSrc,
                                                     const float *__restrict__ W, int Kin) {
    extern __shared__ char smem[];
    uint32_t *a_hi = (uint32_t *)smem;                 // 2048 u32
    uint32_t *a_lo = (uint32_t *)(smem + 8192);
    uint32_t *b_hi = (uint32_t *)(smem + 16384);       // 1024 u32 (x2 regs)
    uint32_t *b_lo = (uint32_t *)(smem + 24576);
    const float *A = useExt ? Aext : pickX(whichSrc);

    int tid = threadIdx.x, wid = tid >> 5, lane = tid & 31;
    int wm = wid & 3, wn = wid >> 2;   // warp coords: 4 in M, 2 in N
    int row0 = blockIdx.x * 128;

    float acc[2][8][4];
#pragma unroll
    for (int mt = 0; mt < 2; ++mt)
#pragma unroll
        for (int nt = 0; nt < 8; ++nt)
#pragma unroll
            for (int q = 0; q < 4; ++q) acc[mt][nt][q] = 0.f;

    int nchunks = Kin >> 5;
    for (int c = 0; c < nchunks; ++c) {
        int k0 = c << 5;
        // ---- stage A tile (128 rows x 32 k) as bf16 hi/lo fragments ----
#pragma unroll
        for (int it = 0; it < 4; ++it) {
            int i = tid + it * 256;            // 0..1023 float4 slots
            int m = i >> 3, kq = i & 7;        // k = kq*4
            int row = row0 + m;
            float4 v = make_float4(0.f, 0.f, 0.f, 0.f);
            if (row < NN) v = *(const float4 *)&A[(size_t)row * Kin + k0 + kq * 4];
            int mt = m >> 4, ks = kq >> 2;
            int kk = (kq & 3) * 4;                       // 0,4,8,12 within k16
            int r = (((m & 15) >= 8) ? 1 : 0) + ((kk >= 8) ? 2 : 0);
            int lane_b = (m & 7) * 4 + ((kk & 7) >> 1);  // 0 or 2 offset
            int base = ((mt * 2 + ks) * 32 + lane_b) * 4 + r;
            uint32_t h0, l0, h1, l1;
            split2_bf16(v.x, v.y, h0, l0);
            split2_bf16(v.z, v.w, h1, l1);
            a_hi[base]     = h0;  a_lo[base]     = l0;
            a_hi[base + 4] = h1;  a_lo[base + 4] = l1;   // lane_b+1
        }
        // ---- stage B tile: B[n][k] = W[k0+k][n], bf16 hi/lo fragments ----
#pragma unroll
        for (int it = 0; it < 8; ++it) {
            int i = tid + it * 256;            // 0..2047 (2 f32 along k each)
            int n = i & 127, kp = i >> 7;      // kp = k-pair index 0..15
            int k = kp * 2;
            float w0 = W[(size_t)(k0 + k) * 128 + n];
            float w1 = W[(size_t)(k0 + k + 1) * 128 + n];
            int nt = n >> 3, ks = k >> 4;
            int kk = k & 15;
            int r = (kk >= 8) ? 1 : 0;
            int lane_b = (n & 7) * 4 + ((kk & 7) >> 1);
            int base = ((nt * 2 + ks) * 32 + lane_b) * 2 + r;
            uint32_t h, l;
            split2_bf16(w0, w1, h, l);
            b_hi[base] = h;  b_lo[base] = l;
        }
        __syncthreads();
        // ---- compute: zero ALU, pure LDS + MMA ----
#pragma unroll
        for (int ks = 0; ks < 2; ++ks) {
            uint32_t ah[2][4], al[2][4];
#pragma unroll
            for (int mt = 0; mt < 2; ++mt) {
                int mtg = wm * 2 + mt;
                uint4 vh = *(const uint4 *)&a_hi[((mtg * 2 + ks) * 32 + lane) * 4];
                uint4 vl = *(const uint4 *)&a_lo[((mtg * 2 + ks) * 32 + lane) * 4];
                ah[mt][0] = vh.x; ah[mt][1] = vh.y; ah[mt][2] = vh.z; ah[mt][3] = vh.w;
                al[mt][0] = vl.x; al[mt][1] = vl.y; al[mt][2] = vl.z; al[mt][3] = vl.w;
            }
#pragma unroll
            for (int nt = 0; nt < 8; ++nt) {
                int ntg = wn * 8 + nt;
                uint2 vh = *(const uint2 *)&b_hi[((ntg * 2 + ks) * 32 + lane) * 2];
                uint2 vl = *(const uint2 *)&b_lo[((ntg * 2 + ks) * 32 + lane) * 2];
                uint32_t bh[2] = {vh.x, vh.y};
                uint32_t bl[2] = {vl.x, vl.y};
#pragma unroll
                for (int mt = 0; mt < 2; ++mt) {
                    mma16816(acc[mt][nt], ah[mt], bh);
                    mma16816(acc[mt][nt], ah[mt], bl);
                    mma16816(acc[mt][nt], al[mt], bh);
                }
            }
        }
        __syncthreads();
    }

    // ---- epilogue: scale by ds[row], store to g_y ----
    int r = lane >> 2;            // 0..7
    int c2 = (lane & 3) * 2;      // 0,2,4,6
#pragma unroll
    for (int mt = 0; mt < 2; ++mt) {
        int rbase = row0 + wm * 32 + mt * 16 + r;
#pragma unroll
        for (int half = 0; half < 2; ++half) {
            int row = rbase + half * 8;
            if (row >= NN) continue;
            float sc = g_ds[row];
            float *dst = &g_y[(size_t)row * 128 + wn * 64 + c2];
#pragma unroll
            for (int nt = 0; nt < 8; ++nt) {
                float2 v;
                v.x = acc[mt][nt][half * 2 + 0] * sc;
                v.y = acc[mt][nt][half * 2 + 1] * sc;
                *(float2 *)(dst + nt * 8) = v;
            }
        }
    }
}

// ------------------------- aggregation: out = relu(ds[d]*(sum_nb y + y[d]) + b) -------------------------
__global__ __launch_bounds__(256) void k_agg(const float *__restrict__ bias, int whichDst) {
    int gw = (blockIdx.x * 256 + threadIdx.x) >> 5;
    int lane = threadIdx.x & 31;
    if (gw >= NN) return;
    float *out = (float *)pickX(whichDst);
    int start = g_rowptr[gw], end = g_rowptr[gw + 1];
    int col = lane * 4;
    float4 acc = *(const float4 *)&g_y[(size_t)gw * 128 + col];  // self term
    int e = start;
    for (; e + 4 <= end; e += 4) {
        int s0 = g_csr[e], s1 = g_csr[e + 1], s2 = g_csr[e + 2], s3 = g_csr[e + 3];
        float4 v0 = *(const float4 *)&g_y[(size_t)s0 * 128 + col];
        float4 v1 = *(const float4 *)&g_y[(size_t)s1 * 128 + col];
        float4 v2 = *(const float4 *)&g_y[(size_t)s2 * 128 + col];
        float4 v3 = *(const float4 *)&g_y[(size_t)s3 * 128 + col];
        acc.x += (v0.x + v1.x) + (v2.x + v3.x);
        acc.y += (v0.y + v1.y) + (v2.y + v3.y);
        acc.z += (v0.z + v1.z) + (v2.z + v3.z);
        acc.w += (v0.w + v1.w) + (v2.w + v3.w);
    }
    for (; e < end; ++e) {
        int s = g_csr[e];
        float4 v = *(const float4 *)&g_y[(size_t)s * 128 + col];
        acc.x += v.x; acc.y += v.y; acc.z += v.z; acc.w += v.w;
    }
    float sc = g_ds[gw];
    float4 b4 = *(const float4 *)&bias[col];
    float4 o;
    o.x = fmaxf(fmaf(acc.x, sc, b4.x), 0.f);
    o.y = fmaxf(fmaf(acc.y, sc, b4.y), 0.f);
    o.z = fmaxf(fmaf(acc.z, sc, b4.z), 0.f);
    o.w = fmaxf(fmaf(acc.w, sc, b4.w), 0.f);
    *(float4 *)&out[(size_t)gw * 128 + col] = o;
}

// ------------------------- score: ys = ds * (cat . Ws), then GCN-aggregate scalar -------------------------
__global__ __launch_bounds__(256) void k_score_lin(const float *__restrict__ Ws) {
    __shared__ float sW[384];
    int tid = threadIdx.x;
    for (int i = tid; i < 384; i += 256) sW[i] = Ws[i];
    __syncthreads();
    int gw = (blockIdx.x * 256 + tid) >> 5;
    int lane = tid & 31;
    if (gw >= NN) return;
    size_t base = (size_t)gw * 128;
    float s = 0.f;
#pragma unroll
    for (int t = 0; t < 4; ++t) {
        int c = lane + 32 * t;
        s += g_x1[base + c] * sW[c] + g_x2[base + c] * sW[128 + c] + g_x3[base + c] * sW[256 + c];
    }
    for (int o = 16; o; o >>= 1) s += __shfl_down_sync(0xFFFFFFFFu, s, o);
    if (lane == 0) g_ysc[gw] = g_ds[gw] * s;
}
__global__ __launch_bounds__(256) void k_score_agg(const float *__restrict__ bs) {
    int gw = (blockIdx.x * 256 + threadIdx.x) >> 5;
    int lane = threadIdx.x & 31;
    if (gw >= NN) return;
    int start = g_rowptr[gw], end = g_rowptr[gw + 1];
    float s = 0.f;
    for (int e = start + lane; e < end; e += 32) s += g_ysc[g_csr[e]];
    for (int o = 16; o; o >>= 1) s += __shfl_down_sync(0xFFFFFFFFu, s, o);
    if (lane == 0) {
        float tot = s + g_ysc[gw];
        float sc = fmaf(g_ds[gw], tot, bs[0]);
        g_score[gw] = sc;
        g_ukey[gw] = fkey(sc);
    }
}

// ------------------------- radix select (4 passes of 8 bits) -------------------------
__global__ void k_hist(int pass) {
    __shared__ unsigned sh[256];
    int t = threadIdx.x;
    sh[t] = 0u; __syncthreads();
    int i = blockIdx.x * 256 + t;
    if (i < NN) {
        unsigned u = g_ukey[i];
        bool m = (pass == 0) || ((u >> (32 - 8 * pass)) == g_prefix);
        if (m) atomicAdd(&sh[(u >> (24 - 8 * pass)) & 255u], 1u);
    }
    __syncthreads();
    if (sh[t]) atomicAdd(&g_hist[t], sh[t]);
}
__global__ void k_select() {
    __shared__ unsigned h[256];
    int t = threadIdx.x;
    h[t] = g_hist[t];
    g_hist[t] = 0u;
    __syncthreads();
    if (t == 0) {
        unsigned kp = g_kprime, c = 0;
        int b;
        for (b = 255; b >= 0; --b) {
            if (c + h[b] >= kp) break;
            c += h[b];
        }
        if (b < 0) b = 0;
        g_prefix = (g_prefix << 8) | (unsigned)b;
        g_kprime = kp - c;
    }
}
__global__ void k_ties() {
    int i = blockIdx.x * blockDim.x + threadIdx.x;
    if (i >= NN) return;
    if (g_ukey[i] == g_prefix) {
        int p = atomicAdd(&g_nties, 1);
        g_tieidx[p] = i;
    }
}
__global__ void k_tieresolve() {
    int M = g_nties;
    unsigned R = g_kprime;
    for (int j = threadIdx.x; j < M; j += blockDim.x) {
        int idx = g_tieidx[j];
        unsigned rank = 0;
        for (int l = 0; l < M; ++l) rank += (g_tieidx[l] < idx) ? 1u : 0u;
        if (rank < R) g_tieflag[idx] = 1;
    }
}

// ------------------------- pooling (max + sum over kept nodes, 384 dims) -------------------------
__global__ __launch_bounds__(384) void k_pool() {
    int c = threadIdx.x;
    const float *xa = (c < 128) ? g_x1 : ((c < 256) ? g_x2 : g_x3);
    int cc = c & 127;
    unsigned T = g_prefix;
    float mx = -3.402823466e38f, sm = 0.f;
    for (int i = blockIdx.x; i < NN; i += gridDim.x) {
        unsigned u = g_ukey[i];
        if (u < T) continue;
        if (u == T && !g_tieflag[i]) continue;
        float g = tanhf(g_score[i]);
        float v = xa[(size_t)i * 128 + cc] * g;
        mx = fmaxf(mx, v);
        sm += v;
    }
    atomicMaxF(&g_gmax[c], mx);
    atomicAdd(&g_gsum[c], sm);
}

// ------------------------- final MLP head (single block) -------------------------
__global__ __launch_bounds__(128) void k_mlp(const float *__restrict__ Wl1, const float *__restrict__ bl1,
                                             const float *__restrict__ Wl2, const float *__restrict__ bl2,
                                             const float *__restrict__ Wl3, const float *__restrict__ bl3,
                                             float *__restrict__ out) {
    __shared__ float h[768], h1[128], h2[64], lg[10];
    int t = threadIdx.x;
    for (int c = t; c < 384; c += 128) {
        h[c] = g_gmax[c];
        h[384 + c] = g_gsum[c] * (1.0f / KKEEP);
    }
    __syncthreads();
    float s = bl1[t];
    for (int i = 0; i < 768; ++i) s = fmaf(h[i], Wl1[i * 128 + t], s);
    h1[t] = fmaxf(s, 0.f);
    __syncthreads();
    if (t < 64) {
        float s2 = bl2[t];
        for (int i = 0; i < 128; ++i) s2 = fmaf(h1[i], Wl2[i * 64 + t], s2);
        h2[t] = fmaxf(s2, 0.f);
    }
    __syncthreads();
    if (t < 10) {
        float s3 = bl3[t];
        for (int i = 0; i < 64; ++i) s3 = fmaf(h2[i], Wl3[i * 10 + t], s3);
        lg[t] = s3;
    }
    __syncthreads();
    if (t == 0) {
        float m = lg[0];
        for (int j = 1; j < 10; ++j) m = fmaxf(m, lg[j]);
        float se = 0.f;
        for (int j = 0; j < 10; ++j) se += expf(lg[j] - m);
        float lse = m + logf(se);
        for (int j = 0; j < 10; ++j) out[j] = lg[j] - lse;
    }
}

// ------------------------- launch -------------------------
extern "C" void kernel_launch(void *const *d_in, const int *in_sizes, int n_in,
                              void *d_out, int out_size) {
    const float *x      = (const float *)d_in[0];
    const int   *ei     = (const int *)d_in[1];   // int32
    const float *W1 = (const float *)d_in[3],  *b1  = (const float *)d_in[4];
    const float *W2 = (const float *)d_in[5],  *b2  = (const float *)d_in[6];
    const float *W3 = (const float *)d_in[7],  *b3  = (const float *)d_in[8];
    const float *Ws = (const float *)d_in[9],  *bs  = (const float *)d_in[10];
    const float *Wl1 = (const float *)d_in[11], *bl1 = (const float *)d_in[12];
    const float *Wl2 = (const float *)d_in[13], *bl2 = (const float *)d_in[14];
    const float *Wl3 = (const float *)d_in[15], *bl3 = (const float *)d_in[16];
    float *out = (float *)d_out;

    const int nblkN = (NN + 255) / 256;
    const int nblkE4 = (EE / 4 + 255) / 256;
    const int nblkW = (NN * 32 + 255) / 256;
    const int nblkT = (NN + 127) / 128;   // gemm blocks (128 rows each)

    cudaFuncSetAttribute(k_gemm_mma, cudaFuncAttributeMaxDynamicSharedMemorySize, GT_SMEM_BYTES);

    // Prologue ordered so the ncu capture slot (4th launch) hits layer-1 gemm.
    k_init<<<nblkN, 256>>>();
    k_count<<<nblkE4, 256>>>(ei);
    k_node<<<nblkN, 256>>>();
    // GCN layer 1 GEMM (needs only g_ds, not CSR)
    k_gemm_mma<<<nblkT, 256, GT_SMEM_BYTES>>>(x, 1, 0, W1, FIN);
    // CSR build
    k_chunksum<<<NCH, 256>>>();
    k_scanchunks<<<1, 1>>>();
    k_scanwrite<<<NCH, 1024>>>();
    k_scatter<<<nblkE4, 256>>>(ei);
    // GCN layer 1 aggregate
    k_agg<<<nblkW, 256>>>(b1, 1);
    // GCN layer 2
    k_gemm_mma<<<nblkT, 256, GT_SMEM_BYTES>>>(nullptr, 0, 1, W2, HH);
    k_agg<<<nblkW, 256>>>(b2, 2);
    // GCN layer 3
    k_gemm_mma<<<nblkT, 256, GT_SMEM_BYTES>>>(nullptr, 0, 2, W3, HH);
    k_agg<<<nblkW, 256>>>(b3, 3);
    // score GCN (1 channel)
    k_score_lin<<<nblkW, 256>>>(Ws);
    k_score_agg<<<nblkW, 256>>>(bs);
    // exact top-k threshold via 4x8-bit radix select
    for (int p = 0; p < 4; ++p) {
        k_hist<<<nblkN, 256>>>(p);
        k_select<<<1, 256>>>();
    }
    k_ties<<<nblkN, 256>>>();
    k_tieresolve<<<1, 256>>>();
    // gated max/mean readout over kept nodes
    k_pool<<<512, 384>>>();
    // MLP head + log_softmax
    k_mlp<<<1, 128>>>(Wl1, bl1, Wl2, bl2, Wl3, bl3, out);
}

// round 8
// speedup vs baseline: 1.7635x; 1.0406x over previous
#include <cuda_runtime.h>
#include <math.h>
#include <stdint.h>

#define NN 100000
#define EE 1600000
#define FIN 512
#define HH 128
#define KKEEP 50000
#define NCH 98  // ceil(NN/1024)

typedef unsigned long long ull;

// ------------------------- device scratch (globals) -------------------------
__device__ __align__(16) float g_y [(size_t)NN * HH];   // scaled xw buffer (y = ds * X@W)
__device__ __align__(16) float g_x1[(size_t)NN * HH];
__device__ __align__(16) float g_x2[(size_t)NN * HH];
__device__ __align__(16) float g_x3[(size_t)NN * HH];
__device__ int   g_degcnt[NN];
__device__ int   g_rowptr[NN + 1];
__device__ int   g_fill[NN];
__device__ int   g_csr[EE];
__device__ int   g_chunksum[NCH];
__device__ int   g_chunkoff[NCH];
__device__ float g_ysc[NN];
__device__ float g_score[NN];
__device__ unsigned g_ukey[NN];
__device__ unsigned g_hist[256];
__device__ unsigned g_prefix;
__device__ unsigned g_kprime;
__device__ int   g_nties;
__device__ int   g_tieidx[NN];
__device__ int   g_tieflag[NN];
__device__ float g_gmax[384];
__device__ float g_gsum[384];
// pre-split B (W^T) fragments, bf16 hi/lo, chunk-major: [chunk][2048]
__device__ __align__(16) uint32_t g_bhi[16 * 2048];
__device__ __align__(16) uint32_t g_blo[16 * 2048];

// ------------------------- small helpers -------------------------
__device__ __forceinline__ unsigned fkey(float f) {
    unsigned u = __float_as_uint(f);
    return (u & 0x80000000u) ? ~u : (u | 0x80000000u);
}
__device__ __forceinline__ void atomicMaxF(float *addr, float val) {
    if (val >= 0.f) atomicMax((int *)addr, __float_as_int(val));
    else            atomicMin((unsigned *)addr, __float_as_uint(val));
}
__device__ __forceinline__ const float *pickX(int w) {
    return w == 1 ? g_x1 : (w == 2 ? g_x2 : g_x3);
}
__device__ __forceinline__ uint32_t pack_bf16x2(float x, float y) {
    uint32_t r;
    asm("cvt.rn.bf16x2.f32 %0, %1, %2;" : "=r"(r) : "f"(y), "f"(x));
    return r;
}
__device__ __forceinline__ float bf16lo_f(uint32_t p) { return __uint_as_float(p << 16); }
__device__ __forceinline__ float bf16hi_f(uint32_t p) { return __uint_as_float(p & 0xFFFF0000u); }
__device__ __forceinline__ void split2_bf16(float x, float y, uint32_t &hi, uint32_t &lo) {
    hi = pack_bf16x2(x, y);
    lo = pack_bf16x2(x - bf16lo_f(hi), y - bf16hi_f(hi));
}
__device__ __forceinline__ void mma16816(float *d, const uint32_t *a, const uint32_t *b) {
    asm volatile("mma.sync.aligned.m16n8k16.row.col.f32.bf16.bf16.f32 "
                 "{%0,%1,%2,%3}, {%4,%5,%6,%7}, {%8,%9}, {%0,%1,%2,%3};"
                 : "+f"(d[0]), "+f"(d[1]), "+f"(d[2]), "+f"(d[3])
                 : "r"(a[0]), "r"(a[1]), "r"(a[2]), "r"(a[3]), "r"(b[0]), "r"(b[1]));
}
#define CP_ASYNC8(dst_u32, src_ptr, szreg) \
    asm volatile("cp.async.ca.shared.global [%0], [%1], 8, %2;" \
                 :: "r"(dst_u32), "l"(src_ptr), "r"(szreg))
#define CP_COMMIT() asm volatile("cp.async.commit_group;" ::: "memory")
#define CP_WAIT1() asm volatile("cp.async.wait_group 1;" ::: "memory")
#define CP_WAIT0() asm volatile("cp.async.wait_group 0;" ::: "memory")

// ------------------------- init -------------------------
__global__ void k_init() {
    int i = blockIdx.x * blockDim.x + threadIdx.x;
    if (i < NN) { g_degcnt[i] = 0; g_fill[i] = 0; g_tieflag[i] = 0; }
    if (i < 384) { g_gmax[i] = -3.402823466e38f; g_gsum[i] = 0.f; }
    if (i < 256) g_hist[i] = 0u;
    if (i == 0) { g_prefix = 0u; g_kprime = (unsigned)KKEEP; g_nties = 0; }
}

// ------------------------- B prep: split W[Kin,128] into fragment-major bf16 hi/lo ----
__global__ void k_prepB(const float *__restrict__ W, int Kin) {
    int i = blockIdx.x * blockDim.x + threadIdx.x;   // pair index
    if (i >= Kin * 64) return;
    int kp = i >> 7, n = i & 127;
    int k = kp * 2;
    float w0 = W[(size_t)k * 128 + n];
    float w1 = W[(size_t)(k + 1) * 128 + n];
    int c = k >> 5;
    int kk = k & 31;
    int nt = n >> 3, ks = kk >> 4;
    int r = ((kk & 15) >= 8) ? 1 : 0;
    int lane_b = (n & 7) * 4 + ((kk & 7) >> 1);
    int base = c * 2048 + ((nt * 2 + ks) * 32 + lane_b) * 2 + r;
    uint32_t h, l;
    split2_bf16(w0, w1, h, l);
    g_bhi[base] = h;
    g_blo[base] = l;
}

// ------------------------- degree / CSR build (edge_index is int32) -------------------------
__global__ void k_count(const int *__restrict__ ei) {
    int e4 = blockIdx.x * blockDim.x + threadIdx.x;
    if (e4 >= EE / 4) return;
    int4 d = *(const int4 *)&ei[EE + e4 * 4];
    atomicAdd(&g_degcnt[d.x], 1);
    atomicAdd(&g_degcnt[d.y], 1);
    atomicAdd(&g_degcnt[d.z], 1);
    atomicAdd(&g_degcnt[d.w], 1);
}
__global__ void k_chunksum() {
    __shared__ int sm[256];
    int t = threadIdx.x, b = blockIdx.x;
    int s = 0;
    for (int j = t; j < 1024; j += 256) {
        int idx = b * 1024 + j;
        if (idx < NN) s += g_degcnt[idx];
    }
    sm[t] = s; __syncthreads();
    for (int o = 128; o; o >>= 1) { if (t < o) sm[t] += sm[t + o]; __syncthreads(); }
    if (t == 0) g_chunksum[b] = sm[0];
}
__global__ void k_scanchunks() {
    int run = 0;
    for (int c = 0; c < NCH; ++c) { g_chunkoff[c] = run; run += g_chunksum[c]; }
    g_rowptr[NN] = EE;
}
__global__ void k_scanwrite() {
    __shared__ int sd[1024];
    int t = threadIdx.x, b = blockIdx.x;
    int idx = b * 1024 + t;
    int v = (idx < NN) ? g_degcnt[idx] : 0;
    int x = v;
    for (int o = 1; o < 1024; o <<= 1) {
        sd[t] = x; __syncthreads();
        if (t >= o) x += sd[t - o];
        __syncthreads();
    }
    if (idx < NN) g_rowptr[idx] = g_chunkoff[b] + x - v;
}
__global__ void k_scatter(const int *__restrict__ ei) {
    int e4 = blockIdx.x * blockDim.x + threadIdx.x;
    if (e4 >= EE / 4) return;
    int4 s = *(const int4 *)&ei[e4 * 4];
    int4 d = *(const int4 *)&ei[EE + e4 * 4];
    g_csr[g_rowptr[d.x] + atomicAdd(&g_fill[d.x], 1)] = s.x;
    g_csr[g_rowptr[d.y] + atomicAdd(&g_fill[d.y], 1)] = s.y;
    g_csr[g_rowptr[d.z] + atomicAdd(&g_fill[d.z], 1)] = s.z;
    g_csr[g_rowptr[d.w] + atomicAdd(&g_fill[d.w], 1)] = s.w;
}

// ------------------------- GEMM: cp.async-pipelined A (f32) + global-L2 B (pre-split) ----
// CTA tile 128x128, BK=32 (2 k16 steps), 8 warps each 32x64 (warp grid 4M x 2N).
// A SMEM (per stage 16KB, 3 stages): f32 fragment-major:
//   fa[((mt*2+ks)*32 + lane)*8 + 2*rowhalf + 4*khalf + j]
// B read directly from g_bhi/g_blo (L2-resident).
#define GPIPE 3
#define GT_SMEM_BYTES (GPIPE * 16384)
__global__ __launch_bounds__(256, 2) void k_gemm_mma(const float *__restrict__ Aext, int useExt,
                                                     int whichSrc, int Kin) {
    extern __shared__ char smem[];
    const float *A = useExt ? Aext : pickX(whichSrc);
    uint32_t sbase = (uint32_t)__cvta_generic_to_shared(smem);

    int tid = threadIdx.x, wid = tid >> 5, lane = tid & 31;
    int wm = wid & 3, wn = wid >> 2;
    int row0 = blockIdx.x * 128;

    // per-thread copy slots: i = tid + it*256, i in [0,2048): m = i>>4 (row), p = i&15 (k-pair)
    int cp_m[8], cp_dst[8];
    const float *cp_src[8];
#pragma unroll
    for (int it = 0; it < 8; ++it) {
        int i = tid + it * 256;
        int m = i >> 4, p = i & 15;
        int mt = m >> 4, ks = p >> 3;
        int l = (m & 7) * 4 + (p & 3);
        int off = 2 * (((m & 15) >= 8) ? 1 : 0) + 4 * (((p & 7) >= 4) ? 1 : 0);
        int fidx = ((mt * 2 + ks) * 32 + l) * 8 + off;
        cp_m[it] = m;
        cp_dst[it] = fidx * 4;                 // byte offset within stage
        cp_src[it] = A + (size_t)(row0 + m) * Kin + p * 2;   // + k0 added per chunk
    }

    float acc[2][8][4];
#pragma unroll
    for (int mt = 0; mt < 2; ++mt)
#pragma unroll
        for (int nt = 0; nt < 8; ++nt)
#pragma unroll
            for (int q = 0; q < 4; ++q) acc[mt][nt][q] = 0.f;

    int nchunks = Kin >> 5;

    // issue copies for a chunk into stage buffer
    auto issue = [&](int c, int buf) {
        uint32_t bb = sbase + buf * 16384;
#pragma unroll
        for (int it = 0; it < 8; ++it) {
            int valid = (row0 + cp_m[it] < NN) ? 8 : 0;
            CP_ASYNC8(bb + cp_dst[it], cp_src[it] + c * 32, valid);
        }
    };

    issue(0, 0); CP_COMMIT();
    issue(1, 1); CP_COMMIT();

    for (int c = 0; c < nchunks; ++c) {
        if (c + 1 < nchunks) { CP_WAIT1(); } else { CP_WAIT0(); }
        __syncthreads();
        if (c + 2 < nchunks) { issue(c + 2, (c + 2) % GPIPE); CP_COMMIT(); }

        const float *fa = (const float *)(smem + (c % GPIPE) * 16384);
#pragma unroll
        for (int ks = 0; ks < 2; ++ks) {
            uint32_t ah[2][4], al[2][4];
#pragma unroll
            for (int mt = 0; mt < 2; ++mt) {
                int mtg = wm * 2 + mt;
                const float4 *p4 = (const float4 *)&fa[((mtg * 2 + ks) * 32 + lane) * 8];
                float4 u = p4[0], v = p4[1];
                split2_bf16(u.x, u.y, ah[mt][0], al[mt][0]);
                split2_bf16(u.z, u.w, ah[mt][1], al[mt][1]);
                split2_bf16(v.x, v.y, ah[mt][2], al[mt][2]);
                split2_bf16(v.z, v.w, ah[mt][3], al[mt][3]);
            }
#pragma unroll
            for (int nt = 0; nt < 8; ++nt) {
                int ntg = wn * 8 + nt;
                int bidx = c * 2048 + ((ntg * 2 + ks) * 32 + lane) * 2;
                uint2 vh = __ldg((const uint2 *)&g_bhi[bidx]);
                uint2 vl = __ldg((const uint2 *)&g_blo[bidx]);
                uint32_t bh[2] = {vh.x, vh.y};
                uint32_t bl[2] = {vl.x, vl.y};
#pragma unroll
                for (int mt = 0; mt < 2; ++mt) {
                    mma16816(acc[mt][nt], ah[mt], bh);
                    mma16816(acc[mt][nt], ah[mt], bl);
                    mma16816(acc[mt][nt], al[mt], bh);
                }
            }
        }
    }

    // ---- epilogue: scale by ds[row] = rsqrt(deg+1), store to g_y ----
    int r = lane >> 2;
    int c2 = (lane & 3) * 2;
#pragma unroll
    for (int mt = 0; mt < 2; ++mt) {
        int rbase = row0 + wm * 32 + mt * 16 + r;
#pragma unroll
        for (int half = 0; half < 2; ++half) {
            int row = rbase + half * 8;
            if (row >= NN) continue;
            float sc = rsqrtf((float)(g_degcnt[row] + 1));
            float *dst = &g_y[(size_t)row * 128 + wn * 64 + c2];
#pragma unroll
            for (int nt = 0; nt < 8; ++nt) {
                float2 v;
                v.x = acc[mt][nt][half * 2 + 0] * sc;
                v.y = acc[mt][nt][half * 2 + 1] * sc;
                *(float2 *)(dst + nt * 8) = v;
            }
        }
    }
}

// ------------------------- aggregation: out = relu(ds[d]*(sum_nb y + y[d]) + b) -------------------------
__global__ __launch_bounds__(256) void k_agg(const float *__restrict__ bias, int whichDst) {
    int gw = (blockIdx.x * 256 + threadIdx.x) >> 5;
    int lane = threadIdx.x & 31;
    if (gw >= NN) return;
    float *out = (float *)pickX(whichDst);
    int start = g_rowptr[gw], end = g_rowptr[gw + 1];
    int col = lane * 4;
    float4 acc = *(const float4 *)&g_y[(size_t)gw * 128 + col];  // self term
    int e = start;
    for (; e + 4 <= end; e += 4) {
        int s0 = g_csr[e], s1 = g_csr[e + 1], s2 = g_csr[e + 2], s3 = g_csr[e + 3];
        float4 v0 = *(const float4 *)&g_y[(size_t)s0 * 128 + col];
        float4 v1 = *(const float4 *)&g_y[(size_t)s1 * 128 + col];
        float4 v2 = *(const float4 *)&g_y[(size_t)s2 * 128 + col];
        float4 v3 = *(const float4 *)&g_y[(size_t)s3 * 128 + col];
        acc.x += (v0.x + v1.x) + (v2.x + v3.x);
        acc.y += (v0.y + v1.y) + (v2.y + v3.y);
        acc.z += (v0.z + v1.z) + (v2.z + v3.z);
        acc.w += (v0.w + v1.w) + (v2.w + v3.w);
    }
    for (; e < end; ++e) {
        int s = g_csr[e];
        float4 v = *(const float4 *)&g_y[(size_t)s * 128 + col];
        acc.x += v.x; acc.y += v.y; acc.z += v.z; acc.w += v.w;
    }
    float sc = rsqrtf((float)(g_degcnt[gw] + 1));
    float4 b4 = *(const float4 *)&bias[col];
    float4 o;
    o.x = fmaxf(fmaf(acc.x, sc, b4.x), 0.f);
    o.y = fmaxf(fmaf(acc.y, sc, b4.y), 0.f);
    o.z = fmaxf(fmaf(acc.z, sc, b4.z), 0.f);
    o.w = fmaxf(fmaf(acc.w, sc, b4.w), 0.f);
    *(float4 *)&out[(size_t)gw * 128 + col] = o;
}

// ------------------------- score: ys = ds * (cat . Ws), then GCN-aggregate scalar -------------------------
__global__ __launch_bounds__(256) void k_score_lin(const float *__restrict__ Ws) {
    __shared__ float sW[384];
    int tid = threadIdx.x;
    for (int i = tid; i < 384; i += 256) sW[i] = Ws[i];
    __syncthreads();
    int gw = (blockIdx.x * 256 + tid) >> 5;
    int lane = tid & 31;
    if (gw >= NN) return;
    size_t base = (size_t)gw * 128;
    float s = 0.f;
#pragma unroll
    for (int t = 0; t < 4; ++t) {
        int c = lane + 32 * t;
        s += g_x1[base + c] * sW[c] + g_x2[base + c] * sW[128 + c] + g_x3[base + c] * sW[256 + c];
    }
    for (int o = 16; o; o >>= 1) s += __shfl_down_sync(0xFFFFFFFFu, s, o);
    if (lane == 0) g_ysc[gw] = rsqrtf((float)(g_degcnt[gw] + 1)) * s;
}
__global__ __launch_bounds__(256) void k_score_agg(const float *__restrict__ bs) {
    int gw = (blockIdx.x * 256 + threadIdx.x) >> 5;
    int lane = threadIdx.x & 31;
    if (gw >= NN) return;
    int start = g_rowptr[gw], end = g_rowptr[gw + 1];
    float s = 0.f;
    for (int e = start + lane; e < end; e += 32) s += g_ysc[g_csr[e]];
    for (int o = 16; o; o >>= 1) s += __shfl_down_sync(0xFFFFFFFFu, s, o);
    if (lane == 0) {
        float tot = s + g_ysc[gw];
        float sc = fmaf(rsqrtf((float)(g_degcnt[gw] + 1)), tot, bs[0]);
        g_score[gw] = sc;
        g_ukey[gw] = fkey(sc);
    }
}

// ------------------------- radix select (4 passes of 8 bits) -------------------------
__global__ void k_hist(int pass) {
    __shared__ unsigned sh[256];
    int t = threadIdx.x;
    sh[t] = 0u; __syncthreads();
    int i = blockIdx.x * 256 + t;
    if (i < NN) {
        unsigned u = g_ukey[i];
        bool m = (pass == 0) || ((u >> (32 - 8 * pass)) == g_prefix);
        if (m) atomicAdd(&sh[(u >> (24 - 8 * pass)) & 255u], 1u);
    }
    __syncthreads();
    if (sh[t]) atomicAdd(&g_hist[t], sh[t]);
}
__global__ void k_select() {
    __shared__ unsigned h[256];
    int t = threadIdx.x;
    h[t] = g_hist[t];
    g_hist[t] = 0u;
    __syncthreads();
    if (t == 0) {
        unsigned kp = g_kprime, c = 0;
        int b;
        for (b = 255; b >= 0; --b) {
            if (c + h[b] >= kp) break;
            c += h[b];
        }
        if (b < 0) b = 0;
        g_prefix = (g_prefix << 8) | (unsigned)b;
        g_kprime = kp - c;
    }
}
__global__ void k_ties() {
    int i = blockIdx.x * blockDim.x + threadIdx.x;
    if (i >= NN) return;
    if (g_ukey[i] == g_prefix) {
        int p = atomicAdd(&g_nties, 1);
        g_tieidx[p] = i;
    }
}
__global__ void k_tieresolve() {
    int M = g_nties;
    unsigned R = g_kprime;
    for (int j = threadIdx.x; j < M; j += blockDim.x) {
        int idx = g_tieidx[j];
        unsigned rank = 0;
        for (int l = 0; l < M; ++l) rank += (g_tieidx[l] < idx) ? 1u : 0u;
        if (rank < R) g_tieflag[idx] = 1;
    }
}

// ------------------------- pooling (max + sum over kept nodes, 384 dims) -------------------------
__global__ __launch_bounds__(384) void k_pool() {
    int c = threadIdx.x;
    const float *xa = (c < 128) ? g_x1 : ((c < 256) ? g_x2 : g_x3);
    int cc = c & 127;
    unsigned T = g_prefix;
    float mx = -3.402823466e38f, sm = 0.f;
    for (int i = blockIdx.x; i < NN; i += gridDim.x) {
        unsigned u = g_ukey[i];
        if (u < T) continue;
        if (u == T && !g_tieflag[i]) continue;
        float g = tanhf(g_score[i]);
        float v = xa[(size_t)i * 128 + cc] * g;
        mx = fmaxf(mx, v);
        sm += v;
    }
    atomicMaxF(&g_gmax[c], mx);
    atomicAdd(&g_gsum[c], sm);
}

// ------------------------- final MLP head (single block) -------------------------
__global__ __launch_bounds__(128) void k_mlp(const float *__restrict__ Wl1, const float *__restrict__ bl1,
                                             const float *__restrict__ Wl2, const float *__restrict__ bl2,
                                             const float *__restrict__ Wl3, const float *__restrict__ bl3,
                                             float *__restrict__ out) {
    __shared__ float h[768], h1[128], h2[64], lg[10];
    int t = threadIdx.x;
    for (int c = t; c < 384; c += 128) {
        h[c] = g_gmax[c];
        h[384 + c] = g_gsum[c] * (1.0f / KKEEP);
    }
    __syncthreads();
    float s = bl1[t];
    for (int i = 0; i < 768; ++i) s = fmaf(h[i], Wl1[i * 128 + t], s);
    h1[t] = fmaxf(s, 0.f);
    __syncthreads();
    if (t < 64) {
        float s2 = bl2[t];
        for (int i = 0; i < 128; ++i) s2 = fmaf(h1[i], Wl2[i * 64 + t], s2);
        h2[t] = fmaxf(s2, 0.f);
    }
    __syncthreads();
    if (t < 10) {
        float s3 = bl3[t];
        for (int i = 0; i < 64; ++i) s3 = fmaf(h2[i], Wl3[i * 10 + t], s3);
        lg[t] = s3;
    }
    __syncthreads();
    if (t == 0) {
        float m = lg[0];
        for (int j = 1; j < 10; ++j) m = fmaxf(m, lg[j]);
        float se = 0.f;
        for (int j = 0; j < 10; ++j) se += expf(lg[j] - m);
        float lse = m + logf(se);
        for (int j = 0; j < 10; ++j) out[j] = lg[j] - lse;
    }
}

// ------------------------- launch -------------------------
extern "C" void kernel_launch(void *const *d_in, const int *in_sizes, int n_in,
                              void *d_out, int out_size) {
    const float *x      = (const float *)d_in[0];
    const int   *ei     = (const int *)d_in[1];   // int32
    const float *W1 = (const float *)d_in[3],  *b1  = (const float *)d_in[4];
    const float *W2 = (const float *)d_in[5],  *b2  = (const float *)d_in[6];
    const float *W3 = (const float *)d_in[7],  *b3  = (const float *)d_in[8];
    const float *Ws = (const float *)d_in[9],  *bs  = (const float *)d_in[10];
    const float *Wl1 = (const float *)d_in[11], *bl1 = (const float *)d_in[12];
    const float *Wl2 = (const float *)d_in[13], *bl2 = (const float *)d_in[14];
    const float *Wl3 = (const float *)d_in[15], *bl3 = (const float *)d_in[16];
    float *out = (float *)d_out;

    const int nblkN = (NN + 255) / 256;
    const int nblkE4 = (EE / 4 + 255) / 256;
    const int nblkW = (NN * 32 + 255) / 256;
    const int nblkT = (NN + 127) / 128;

    cudaFuncSetAttribute(k_gemm_mma, cudaFuncAttributeMaxDynamicSharedMemorySize, GT_SMEM_BYTES);

    // Prologue ordered so the ncu capture slot (4th launch) hits layer-1 gemm.
    k_init<<<nblkN, 256>>>();
    k_prepB<<<(FIN * 64 + 255) / 256, 256>>>(W1, FIN);
    k_count<<<nblkE4, 256>>>(ei);
    // GCN layer 1 GEMM
    k_gemm_mma<<<nblkT, 256, GT_SMEM_BYTES>>>(x, 1, 0, FIN);
    // CSR build
    k_chunksum<<<NCH, 256>>>();
    k_scanchunks<<<1, 1>>>();
    k_scanwrite<<<NCH, 1024>>>();
    k_scatter<<<nblkE4, 256>>>(ei);
    // GCN layer 1 aggregate
    k_agg<<<nblkW, 256>>>(b1, 1);
    // GCN layer 2
    k_prepB<<<(HH * 64 + 255) / 256, 256>>>(W2, HH);
    k_gemm_mma<<<nblkT, 256, GT_SMEM_BYTES>>>(nullptr, 0, 1, HH);
    k_agg<<<nblkW, 256>>>(b2, 2);
    // GCN layer 3
    k_prepB<<<(HH * 64 + 255) / 256, 256>>>(W3, HH);
    k_gemm_mma<<<nblkT, 256, GT_SMEM_BYTES>>>(nullptr, 0, 2, HH);
    k_agg<<<nblkW, 256>>>(b3, 3);
    // score GCN (1 channel)
    k_score_lin<<<nblkW, 256>>>(Ws);
    k_score_agg<<<nblkW, 256>>>(bs);
    // exact top-k threshold via 4x8-bit radix select
    for (int p = 0; p < 4; ++p) {
        k_hist<<<nblkN, 256>>>(p);
        k_select<<<1, 256>>>();
    }
    k_ties<<<nblkN, 256>>>();
    k_tieresolve<<<1, 256>>>();
    // gated max/mean readout over kept nodes
    k_pool<<<512, 384>>>();
    // MLP head + log_softmax
    k_mlp<<<1, 128>>>(Wl1, bl1, Wl2, bl2, Wl3, bl3, out);
}

// round 9
// speedup vs baseline: 1.8985x; 1.0765x over previous
#include <cuda_runtime.h>
#include <math.h>
#include <stdint.h>

#define NN 100000
#define EE 1600000
#define FIN 512
#define HH 128
#define KKEEP 50000
#define NCH 98  // ceil(NN/1024)

typedef unsigned long long ull;

// ------------------------- device scratch (globals) -------------------------
__device__ __align__(16) float g_y [(size_t)NN * HH];   // scaled xw buffer (y = ds * X@W)
__device__ __align__(16) float g_x1[(size_t)NN * HH];
__device__ __align__(16) float g_x2[(size_t)NN * HH];
__device__ __align__(16) float g_x3[(size_t)NN * HH];
__device__ int   g_degcnt[NN];
__device__ int   g_rowptr[NN + 1];
__device__ int   g_fill[NN];
__device__ int   g_csr[EE];
__device__ int   g_chunksum[NCH];
__device__ int   g_chunkoff[NCH];
__device__ float g_ysc[NN];
__device__ float g_score[NN];
__device__ unsigned g_ukey[NN];
__device__ unsigned g_hist[256];
__device__ unsigned g_prefix;
__device__ unsigned g_kprime;
__device__ int   g_nties;
__device__ int   g_tieidx[NN];
__device__ int   g_tieflag[NN];
__device__ float g_gmax[384];
__device__ float g_gsum[384];
// pre-split B (W^T) fragments, bf16 hi/lo, chunk-major: [chunk][2048]
__device__ __align__(16) uint32_t g_bhi[16 * 2048];
__device__ __align__(16) uint32_t g_blo[16 * 2048];

// ------------------------- small helpers -------------------------
__device__ __forceinline__ unsigned fkey(float f) {
    unsigned u = __float_as_uint(f);
    return (u & 0x80000000u) ? ~u : (u | 0x80000000u);
}
__device__ __forceinline__ void atomicMaxF(float *addr, float val) {
    if (val >= 0.f) atomicMax((int *)addr, __float_as_int(val));
    else            atomicMin((unsigned *)addr, __float_as_uint(val));
}
__device__ __forceinline__ const float *pickX(int w) {
    return w == 1 ? g_x1 : (w == 2 ? g_x2 : g_x3);
}
__device__ __forceinline__ uint32_t pack_bf16x2(float x, float y) {
    uint32_t r;
    asm("cvt.rn.bf16x2.f32 %0, %1, %2;" : "=r"(r) : "f"(y), "f"(x));
    return r;
}
__device__ __forceinline__ float bf16lo_f(uint32_t p) { return __uint_as_float(p << 16); }
__device__ __forceinline__ float bf16hi_f(uint32_t p) { return __uint_as_float(p & 0xFFFF0000u); }
__device__ __forceinline__ void split2_bf16(float x, float y, uint32_t &hi, uint32_t &lo) {
    hi = pack_bf16x2(x, y);
    lo = pack_bf16x2(x - bf16lo_f(hi), y - bf16hi_f(hi));
}
__device__ __forceinline__ void mma16816(float *d, const uint32_t *a, const uint32_t *b) {
    asm volatile("mma.sync.aligned.m16n8k16.row.col.f32.bf16.bf16.f32 "
                 "{%0,%1,%2,%3}, {%4,%5,%6,%7}, {%8,%9}, {%0,%1,%2,%3};"
                 : "+f"(d[0]), "+f"(d[1]), "+f"(d[2]), "+f"(d[3])
                 : "r"(a[0]), "r"(a[1]), "r"(a[2]), "r"(a[3]), "r"(b[0]), "r"(b[1]));
}
#define CP_ASYNC8(dst_u32, src_ptr, szreg) \
    asm volatile("cp.async.ca.shared.global [%0], [%1], 8, %2;" \
                 :: "r"(dst_u32), "l"(src_ptr), "r"(szreg))
#define CP_ASYNC16(dst_u32, src_ptr) \
    asm volatile("cp.async.cg.shared.global [%0], [%1], 16;" \
                 :: "r"(dst_u32), "l"(src_ptr))
#define CP_COMMIT() asm volatile("cp.async.commit_group;" ::: "memory")
#define CP_WAIT1() asm volatile("cp.async.wait_group 1;" ::: "memory")
#define CP_WAIT0() asm volatile("cp.async.wait_group 0;" ::: "memory")

// ------------------------- init -------------------------
__global__ void k_init() {
    int i = blockIdx.x * blockDim.x + threadIdx.x;
    if (i < NN) { g_degcnt[i] = 0; g_fill[i] = 0; g_tieflag[i] = 0; }
    if (i < 384) { g_gmax[i] = -3.402823466e38f; g_gsum[i] = 0.f; }
    if (i < 256) g_hist[i] = 0u;
    if (i == 0) { g_prefix = 0u; g_kprime = (unsigned)KKEEP; g_nties = 0; }
}

// ------------------------- B prep: split W[Kin,128] into fragment-major bf16 hi/lo ----
__global__ void k_prepB(const float *__restrict__ W, int Kin) {
    int i = blockIdx.x * blockDim.x + threadIdx.x;   // pair index
    if (i >= Kin * 64) return;
    int kp = i >> 7, n = i & 127;
    int k = kp * 2;
    float w0 = W[(size_t)k * 128 + n];
    float w1 = W[(size_t)(k + 1) * 128 + n];
    int c = k >> 5;
    int kk = k & 31;
    int nt = n >> 3, ks = kk >> 4;
    int r = ((kk & 15) >= 8) ? 1 : 0;
    int lane_b = (n & 7) * 4 + ((kk & 7) >> 1);
    int base = c * 2048 + ((nt * 2 + ks) * 32 + lane_b) * 2 + r;
    uint32_t h, l;
    split2_bf16(w0, w1, h, l);
    g_bhi[base] = h;
    g_blo[base] = l;
}

// ------------------------- degree / CSR build (edge_index is int32) -------------------------
__global__ void k_count(const int *__restrict__ ei) {
    int e4 = blockIdx.x * blockDim.x + threadIdx.x;
    if (e4 >= EE / 4) return;
    int4 d = *(const int4 *)&ei[EE + e4 * 4];
    atomicAdd(&g_degcnt[d.x], 1);
    atomicAdd(&g_degcnt[d.y], 1);
    atomicAdd(&g_degcnt[d.z], 1);
    atomicAdd(&g_degcnt[d.w], 1);
}
__global__ void k_chunksum() {
    __shared__ int sm[256];
    int t = threadIdx.x, b = blockIdx.x;
    int s = 0;
    for (int j = t; j < 1024; j += 256) {
        int idx = b * 1024 + j;
        if (idx < NN) s += g_degcnt[idx];
    }
    sm[t] = s; __syncthreads();
    for (int o = 128; o; o >>= 1) { if (t < o) sm[t] += sm[t + o]; __syncthreads(); }
    if (t == 0) g_chunksum[b] = sm[0];
}
__global__ void k_scanchunks() {
    int run = 0;
    for (int c = 0; c < NCH; ++c) { g_chunkoff[c] = run; run += g_chunksum[c]; }
    g_rowptr[NN] = EE;
}
__global__ void k_scanwrite() {
    __shared__ int sd[1024];
    int t = threadIdx.x, b = blockIdx.x;
    int idx = b * 1024 + t;
    int v = (idx < NN) ? g_degcnt[idx] : 0;
    int x = v;
    for (int o = 1; o < 1024; o <<= 1) {
        sd[t] = x; __syncthreads();
        if (t >= o) x += sd[t - o];
        __syncthreads();
    }
    if (idx < NN) g_rowptr[idx] = g_chunkoff[b] + x - v;
}
__global__ void k_scatter(const int *__restrict__ ei) {
    int e4 = blockIdx.x * blockDim.x + threadIdx.x;
    if (e4 >= EE / 4) return;
    int4 s = *(const int4 *)&ei[e4 * 4];
    int4 d = *(const int4 *)&ei[EE + e4 * 4];
    g_csr[g_rowptr[d.x] + atomicAdd(&g_fill[d.x], 1)] = s.x;
    g_csr[g_rowptr[d.y] + atomicAdd(&g_fill[d.y], 1)] = s.y;
    g_csr[g_rowptr[d.z] + atomicAdd(&g_fill[d.z], 1)] = s.z;
    g_csr[g_rowptr[d.w] + atomicAdd(&g_fill[d.w], 1)] = s.w;
}

// ------------------------- GEMM: cp.async pipeline carrying A (f32) + B hi/lo (bf16) ----
// CTA tile 128x128, BK=32 (2 k16 steps), 8 warps each 32x64 (warp grid 4M x 2N).
// Stage (32KB): [A f32 frag 16KB][Bhi 8KB][Blo 8KB], 3 stages.
#define GPIPE 3
#define GSTAGE 32768
#define GT_SMEM_BYTES (GPIPE * GSTAGE)
__global__ __launch_bounds__(256, 2) void k_gemm_mma(const float *__restrict__ Aext, int useExt,
                                                     int whichSrc, int Kin) {
    extern __shared__ char smem[];
    const float *A = useExt ? Aext : pickX(whichSrc);
    uint32_t sbase = (uint32_t)__cvta_generic_to_shared(smem);

    int tid = threadIdx.x, wid = tid >> 5, lane = tid & 31;
    int wm = wid & 3, wn = wid >> 2;
    int row0 = blockIdx.x * 128;

    // per-thread A copy slots: i = tid + it*256, i in [0,2048): m = i>>4 (row), p = i&15 (k-pair)
    int cp_m[8], cp_dst[8];
    const float *cp_src[8];
#pragma unroll
    for (int it = 0; it < 8; ++it) {
        int i = tid + it * 256;
        int m = i >> 4, p = i & 15;
        int mt = m >> 4, ks = p >> 3;
        int l = (m & 7) * 4 + (p & 3);
        int off = 2 * (((m & 15) >= 8) ? 1 : 0) + 4 * (((p & 7) >= 4) ? 1 : 0);
        int fidx = ((mt * 2 + ks) * 32 + l) * 8 + off;
        cp_m[it] = m;
        cp_dst[it] = fidx * 4;
        cp_src[it] = A + (size_t)(row0 + m) * Kin + p * 2;
    }

    float acc[2][8][4];
#pragma unroll
    for (int mt = 0; mt < 2; ++mt)
#pragma unroll
        for (int nt = 0; nt < 8; ++nt)
#pragma unroll
            for (int q = 0; q < 4; ++q) acc[mt][nt][q] = 0.f;

    int nchunks = Kin >> 5;

    auto issue = [&](int c, int buf) {
        uint32_t bb = sbase + buf * GSTAGE;
#pragma unroll
        for (int it = 0; it < 8; ++it) {
            int valid = (row0 + cp_m[it] < NN) ? 8 : 0;
            CP_ASYNC8(bb + cp_dst[it], cp_src[it] + c * 32, valid);
        }
        // B hi/lo: 2048 u32 each = 512 x 16B; 2 per thread per array
#pragma unroll
        for (int j = 0; j < 2; ++j) {
            int idx = tid + j * 256;          // 0..511
            CP_ASYNC16(bb + 16384 + idx * 16, (const char *)&g_bhi[c * 2048 + idx * 4]);
            CP_ASYNC16(bb + 24576 + idx * 16, (const char *)&g_blo[c * 2048 + idx * 4]);
        }
    };

    issue(0, 0); CP_COMMIT();
    issue(1, 1); CP_COMMIT();

    for (int c = 0; c < nchunks; ++c) {
        if (c + 1 < nchunks) { CP_WAIT1(); } else { CP_WAIT0(); }
        __syncthreads();
        if (c + 2 < nchunks) { issue(c + 2, (c + 2) % GPIPE); CP_COMMIT(); }

        const char *stg = smem + (c % GPIPE) * GSTAGE;
        const float *fa = (const float *)stg;
        const uint32_t *fbh = (const uint32_t *)(stg + 16384);
        const uint32_t *fbl = (const uint32_t *)(stg + 24576);
#pragma unroll
        for (int ks = 0; ks < 2; ++ks) {
            uint32_t ah[2][4], al[2][4];
#pragma unroll
            for (int mt = 0; mt < 2; ++mt) {
                int mtg = wm * 2 + mt;
                const float4 *p4 = (const float4 *)&fa[((mtg * 2 + ks) * 32 + lane) * 8];
                float4 u = p4[0], v = p4[1];
                split2_bf16(u.x, u.y, ah[mt][0], al[mt][0]);
                split2_bf16(u.z, u.w, ah[mt][1], al[mt][1]);
                split2_bf16(v.x, v.y, ah[mt][2], al[mt][2]);
                split2_bf16(v.z, v.w, ah[mt][3], al[mt][3]);
            }
#pragma unroll
            for (int nt = 0; nt < 8; ++nt) {
                int ntg = wn * 8 + nt;
                int bidx = ((ntg * 2 + ks) * 32 + lane) * 2;
                uint2 vh = *(const uint2 *)&fbh[bidx];
                uint2 vl = *(const uint2 *)&fbl[bidx];
                uint32_t bh[2] = {vh.x, vh.y};
                uint32_t bl[2] = {vl.x, vl.y};
#pragma unroll
                for (int mt = 0; mt < 2; ++mt) {
                    mma16816(acc[mt][nt], ah[mt], bh);
                    mma16816(acc[mt][nt], ah[mt], bl);
                    mma16816(acc[mt][nt], al[mt], bh);
                }
            }
        }
    }

    // ---- epilogue: scale by ds[row] = rsqrt(deg+1), store to g_y ----
    int r = lane >> 2;
    int c2 = (lane & 3) * 2;
#pragma unroll
    for (int mt = 0; mt < 2; ++mt) {
        int rbase = row0 + wm * 32 + mt * 16 + r;
#pragma unroll
        for (int half = 0; half < 2; ++half) {
            int row = rbase + half * 8;
            if (row >= NN) continue;
            float sc = rsqrtf((float)(g_degcnt[row] + 1));
            float *dst = &g_y[(size_t)row * 128 + wn * 64 + c2];
#pragma unroll
            for (int nt = 0; nt < 8; ++nt) {
                float2 v;
                v.x = acc[mt][nt][half * 2 + 0] * sc;
                v.y = acc[mt][nt][half * 2 + 1] * sc;
                *(float2 *)(dst + nt * 8) = v;
            }
        }
    }
}

// ------------------------- aggregation: out = relu(ds[d]*(sum_nb y + y[d]) + b) -------------------------
__global__ __launch_bounds__(256) void k_agg(const float *__restrict__ bias, int whichDst) {
    int gw = (blockIdx.x * 256 + threadIdx.x) >> 5;
    int lane = threadIdx.x & 31;
    if (gw >= NN) return;
    float *out = (float *)pickX(whichDst);
    int start = g_rowptr[gw], end = g_rowptr[gw + 1];
    int col = lane * 4;
    float4 acc = *(const float4 *)&g_y[(size_t)gw * 128 + col];  // self term
    int e = start;
    for (; e + 4 <= end; e += 4) {
        int s0 = g_csr[e], s1 = g_csr[e + 1], s2 = g_csr[e + 2], s3 = g_csr[e + 3];
        float4 v0 = *(const float4 *)&g_y[(size_t)s0 * 128 + col];
        float4 v1 = *(const float4 *)&g_y[(size_t)s1 * 128 + col];
        float4 v2 = *(const float4 *)&g_y[(size_t)s2 * 128 + col];
        float4 v3 = *(const float4 *)&g_y[(size_t)s3 * 128 + col];
        acc.x += (v0.x + v1.x) + (v2.x + v3.x);
        acc.y += (v0.y + v1.y) + (v2.y + v3.y);
        acc.z += (v0.z + v1.z) + (v2.z + v3.z);
        acc.w += (v0.w + v1.w) + (v2.w + v3.w);
    }
    for (; e < end; ++e) {
        int s = g_csr[e];
        float4 v = *(const float4 *)&g_y[(size_t)s * 128 + col];
        acc.x += v.x; acc.y += v.y; acc.z += v.z; acc.w += v.w;
    }
    float sc = rsqrtf((float)(g_degcnt[gw] + 1));
    float4 b4 = *(const float4 *)&bias[col];
    float4 o;
    o.x = fmaxf(fmaf(acc.x, sc, b4.x), 0.f);
    o.y = fmaxf(fmaf(acc.y, sc, b4.y), 0.f);
    o.z = fmaxf(fmaf(acc.z, sc, b4.z), 0.f);
    o.w = fmaxf(fmaf(acc.w, sc, b4.w), 0.f);
    *(float4 *)&out[(size_t)gw * 128 + col] = o;
}

// ------------------------- score: ys = ds * (cat . Ws), then GCN-aggregate scalar -------------------------
__global__ __launch_bounds__(256) void k_score_lin(const float *__restrict__ Ws) {
    __shared__ float sW[384];
    int tid = threadIdx.x;
    for (int i = tid; i < 384; i += 256) sW[i] = Ws[i];
    __syncthreads();
    int gw = (blockIdx.x * 256 + tid) >> 5;
    int lane = tid & 31;
    if (gw >= NN) return;
    size_t base = (size_t)gw * 128;
    float s = 0.f;
#pragma unroll
    for (int t = 0; t < 4; ++t) {
        int c = lane + 32 * t;
        s += g_x1[base + c] * sW[c] + g_x2[base + c] * sW[128 + c] + g_x3[base + c] * sW[256 + c];
    }
    for (int o = 16; o; o >>= 1) s += __shfl_down_sync(0xFFFFFFFFu, s, o);
    if (lane == 0) g_ysc[gw] = rsqrtf((float)(g_degcnt[gw] + 1)) * s;
}
__global__ __launch_bounds__(256) void k_score_agg(const float *__restrict__ bs) {
    int gw = (blockIdx.x * 256 + threadIdx.x) >> 5;
    int lane = threadIdx.x & 31;
    if (gw >= NN) return;
    int start = g_rowptr[gw], end = g_rowptr[gw + 1];
    float s = 0.f;
    for (int e = start + lane; e < end; e += 32) s += g_ysc[g_csr[e]];
    for (int o = 16; o; o >>= 1) s += __shfl_down_sync(0xFFFFFFFFu, s, o);
    if (lane == 0) {
        float tot = s + g_ysc[gw];
        float sc = fmaf(rsqrtf((float)(g_degcnt[gw] + 1)), tot, bs[0]);
        g_score[gw] = sc;
        g_ukey[gw] = fkey(sc);
    }
}

// ------------------------- radix select (4 passes of 8 bits) -------------------------
__global__ void k_hist(int pass) {
    __shared__ unsigned sh[256];
    int t = threadIdx.x;
    sh[t] = 0u; __syncthreads();
    int i = blockIdx.x * 256 + t;
    if (i < NN) {
        unsigned u = g_ukey[i];
        bool m = (pass == 0) || ((u >> (32 - 8 * pass)) == g_prefix);
        if (m) atomicAdd(&sh[(u >> (24 - 8 * pass)) & 255u], 1u);
    }
    __syncthreads();
    if (sh[t]) atomicAdd(&g_hist[t], sh[t]);
}
__global__ void k_select() {
    __shared__ unsigned h[256];
    int t = threadIdx.x;
    h[t] = g_hist[t];
    g_hist[t] = 0u;
    __syncthreads();
    if (t == 0) {
        unsigned kp = g_kprime, c = 0;
        int b;
        for (b = 255; b >= 0; --b) {
            if (c + h[b] >= kp) break;
            c += h[b];
        }
        if (b < 0) b = 0;
        g_prefix = (g_prefix << 8) | (unsigned)b;
        g_kprime = kp - c;
    }
}
__global__ void k_ties() {
    int i = blockIdx.x * blockDim.x + threadIdx.x;
    if (i >= NN) return;
    if (g_ukey[i] == g_prefix) {
        int p = atomicAdd(&g_nties, 1);
        g_tieidx[p] = i;
    }
}
__global__ void k_tieresolve() {
    int M = g_nties;
    unsigned R = g_kprime;
    for (int j = threadIdx.x; j < M; j += blockDim.x) {
        int idx = g_tieidx[j];
        unsigned rank = 0;
        for (int l = 0; l < M; ++l) rank += (g_tieidx[l] < idx) ? 1u : 0u;
        if (rank < R) g_tieflag[idx] = 1;
    }
}

// ------------------------- pooling (max + sum over kept nodes, 384 dims) -------------------------
__global__ __launch_bounds__(384) void k_pool() {
    int c = threadIdx.x;
    const float *xa = (c < 128) ? g_x1 : ((c < 256) ? g_x2 : g_x3);
    int cc = c & 127;
    unsigned T = g_prefix;
    float mx = -3.402823466e38f, sm = 0.f;
    for (int i = blockIdx.x; i < NN; i += gridDim.x) {
        unsigned u = g_ukey[i];
        if (u < T) continue;
        if (u == T && !g_tieflag[i]) continue;
        float g = tanhf(g_score[i]);
        float v = xa[(size_t)i * 128 + cc] * g;
        mx = fmaxf(mx, v);
        sm += v;
    }
    atomicMaxF(&g_gmax[c], mx);
    atomicAdd(&g_gsum[c], sm);
}

// ------------------------- final MLP head (single block) -------------------------
__global__ __launch_bounds__(128) void k_mlp(const float *__restrict__ Wl1, const float *__restrict__ bl1,
                                             const float *__restrict__ Wl2, const float *__restrict__ bl2,
                                             const float *__restrict__ Wl3, const float *__restrict__ bl3,
                                             float *__restrict__ out) {
    __shared__ float h[768], h1[128], h2[64], lg[10];
    int t = threadIdx.x;
    for (int c = t; c < 384; c += 128) {
        h[c] = g_gmax[c];
        h[384 + c] = g_gsum[c] * (1.0f / KKEEP);
    }
    __syncthreads();
    float s = bl1[t];
    for (int i = 0; i < 768; ++i) s = fmaf(h[i], Wl1[i * 128 + t], s);
    h1[t] = fmaxf(s, 0.f);
    __syncthreads();
    if (t < 64) {
        float s2 = bl2[t];
        for (int i = 0; i < 128; ++i) s2 = fmaf(h1[i], Wl2[i * 64 + t], s2);
        h2[t] = fmaxf(s2, 0.f);
    }
    __syncthreads();
    if (t < 10) {
        float s3 = bl3[t];
        for (int i = 0; i < 64; ++i) s3 = fmaf(h2[i], Wl3[i * 10 + t], s3);
        lg[t] = s3;
    }
    __syncthreads();
    if (t == 0) {
        float m = lg[0];
        for (int j = 1; j < 10; ++j) m = fmaxf(m, lg[j]);
        float se = 0.f;
        for (int j = 0; j < 10; ++j) se += expf(lg[j] - m);
        float lse = m + logf(se);
        for (int j = 0; j < 10; ++j) out[j] = lg[j] - lse;
    }
}

// ------------------------- launch -------------------------
extern "C" void kernel_launch(void *const *d_in, const int *in_sizes, int n_in,
                              void *d_out, int out_size) {
    const float *x      = (const float *)d_in[0];
    const int   *ei     = (const int *)d_in[1];   // int32
    const float *W1 = (const float *)d_in[3],  *b1  = (const float *)d_in[4];
    const float *W2 = (const float *)d_in[5],  *b2  = (const float *)d_in[6];
    const float *W3 = (const float *)d_in[7],  *b3  = (const float *)d_in[8];
    const float *Ws = (const float *)d_in[9],  *bs  = (const float *)d_in[10];
    const float *Wl1 = (const float *)d_in[11], *bl1 = (const float *)d_in[12];
    const float *Wl2 = (const float *)d_in[13], *bl2 = (const float *)d_in[14];
    const float *Wl3 = (const float *)d_in[15], *bl3 = (const float *)d_in[16];
    float *out = (float *)d_out;

    const int nblkN = (NN + 255) / 256;
    const int nblkE4 = (EE / 4 + 255) / 256;
    const int nblkW = (NN * 32 + 255) / 256;
    const int nblkT = (NN + 127) / 128;

    cudaFuncSetAttribute(k_gemm_mma, cudaFuncAttributeMaxDynamicSharedMemorySize, GT_SMEM_BYTES);

    // Prologue ordered so the ncu capture slot (4th launch) hits layer-1 gemm.
    k_init<<<nblkN, 256>>>();
    k_prepB<<<(FIN * 64 + 255) / 256, 256>>>(W1, FIN);
    k_count<<<nblkE4, 256>>>(ei);
    // GCN layer 1 GEMM
    k_gemm_mma<<<nblkT, 256, GT_SMEM_BYTES>>>(x, 1, 0, FIN);
    // CSR build
    k_chunksum<<<NCH, 256>>>();
    k_scanchunks<<<1, 1>>>();
    k_scanwrite<<<NCH, 1024>>>();
    k_scatter<<<nblkE4, 256>>>(ei);
    // GCN layer 1 aggregate
    k_agg<<<nblkW, 256>>>(b1, 1);
    // GCN layer 2
    k_prepB<<<(HH * 64 + 255) / 256, 256>>>(W2, HH);
    k_gemm_mma<<<nblkT, 256, GT_SMEM_BYTES>>>(nullptr, 0, 1, HH);
    k_agg<<<nblkW, 256>>>(b2, 2);
    // GCN layer 3
    k_prepB<<<(HH * 64 + 255) / 256, 256>>>(W3, HH);
    k_gemm_mma<<<nblkT, 256, GT_SMEM_BYTES>>>(nullptr, 0, 2, HH);
    k_agg<<<nblkW, 256>>>(b3, 3);
    // score GCN (1 channel)
    k_score_lin<<<nblkW, 256>>>(Ws);
    k_score_agg<<<nblkW, 256>>>(bs);
    // exact top-k threshold via 4x8-bit radix select
    for (int p = 0; p < 4; ++p) {
        k_hist<<<nblkN, 256>>>(p);
        k_select<<<1, 256>>>();
    }
    k_ties<<<nblkN, 256>>>();
    k_tieresolve<<<1, 256>>>();
    // gated max/mean readout over kept nodes
    k_pool<<<512, 384>>>();
    // MLP head + log_softmax
    k_mlp<<<1, 128>>>(Wl1, bl1, Wl2, bl2, Wl3, bl3, out);
}

// round 10
// speedup vs baseline: 1.9705x; 1.0380x over previous
#include <cuda_runtime.h>
#include <cuda_fp16.h>
#include <math.h>
#include <stdint.h>

#define NN 100000
#define EE 1600000
#define FIN 512
#define HH 128
#define KKEEP 50000
#define NCH 98  // ceil(NN/1024)

typedef unsigned long long ull;

// ------------------------- device scratch (globals) -------------------------
__device__ __align__(16) uint32_t g_yh[(size_t)NN * 64];  // y as half2 pairs (fp16 gather buffer)
__device__ __align__(16) float g_x1[(size_t)NN * HH];
__device__ __align__(16) float g_x2[(size_t)NN * HH];
__device__ __align__(16) float g_x3[(size_t)NN * HH];
__device__ int   g_degcnt[NN];
__device__ int   g_rowptr[NN + 1];
__device__ int   g_fill[NN];
__device__ int   g_csr[EE];
__device__ int   g_chunksum[NCH];
__device__ int   g_chunkoff[NCH];
__device__ float g_ysc[NN];
__device__ float g_score[NN];
__device__ unsigned g_ukey[NN];
__device__ unsigned g_hist[256];
__device__ unsigned g_prefix;
__device__ unsigned g_kprime;
__device__ int   g_nties;
__device__ int   g_tieidx[NN];
__device__ int   g_tieflag[NN];
__device__ float g_gmax[384];
__device__ float g_gsum[384];
// pre-split B (W^T) fragments, bf16 hi/lo, chunk-major: [chunk][2048]
__device__ __align__(16) uint32_t g_bhi[16 * 2048];
__device__ __align__(16) uint32_t g_blo[16 * 2048];

// ------------------------- small helpers -------------------------
__device__ __forceinline__ unsigned fkey(float f) {
    unsigned u = __float_as_uint(f);
    return (u & 0x80000000u) ? ~u : (u | 0x80000000u);
}
__device__ __forceinline__ void atomicMaxF(float *addr, float val) {
    if (val >= 0.f) atomicMax((int *)addr, __float_as_int(val));
    else            atomicMin((unsigned *)addr, __float_as_uint(val));
}
__device__ __forceinline__ const float *pickX(int w) {
    return w == 1 ? g_x1 : (w == 2 ? g_x2 : g_x3);
}
__device__ __forceinline__ uint32_t pack_bf16x2(float x, float y) {
    uint32_t r;
    asm("cvt.rn.bf16x2.f32 %0, %1, %2;" : "=r"(r) : "f"(y), "f"(x));
    return r;
}
__device__ __forceinline__ float bf16lo_f(uint32_t p) { return __uint_as_float(p << 16); }
__device__ __forceinline__ float bf16hi_f(uint32_t p) { return __uint_as_float(p & 0xFFFF0000u); }
__device__ __forceinline__ void split2_bf16(float x, float y, uint32_t &hi, uint32_t &lo) {
    hi = pack_bf16x2(x, y);
    lo = pack_bf16x2(x - bf16lo_f(hi), y - bf16hi_f(hi));
}
__device__ __forceinline__ void mma16816(float *d, const uint32_t *a, const uint32_t *b) {
    asm volatile("mma.sync.aligned.m16n8k16.row.col.f32.bf16.bf16.f32 "
                 "{%0,%1,%2,%3}, {%4,%5,%6,%7}, {%8,%9}, {%0,%1,%2,%3};"
                 : "+f"(d[0]), "+f"(d[1]), "+f"(d[2]), "+f"(d[3])
                 : "r"(a[0]), "r"(a[1]), "r"(a[2]), "r"(a[3]), "r"(b[0]), "r"(b[1]));
}
#define CP_ASYNC8(dst_u32, src_ptr, szreg) \
    asm volatile("cp.async.ca.shared.global [%0], [%1], 8, %2;" \
                 :: "r"(dst_u32), "l"(src_ptr), "r"(szreg))
#define CP_ASYNC16(dst_u32, src_ptr) \
    asm volatile("cp.async.cg.shared.global [%0], [%1], 16;" \
                 :: "r"(dst_u32), "l"(src_ptr))
#define CP_COMMIT() asm volatile("cp.async.commit_group;" ::: "memory")
#define CP_WAIT1() asm volatile("cp.async.wait_group 1;" ::: "memory")
#define CP_WAIT0() asm volatile("cp.async.wait_group 0;" ::: "memory")

// ------------------------- init -------------------------
__global__ void k_init() {
    int i = blockIdx.x * blockDim.x + threadIdx.x;
    if (i < NN) { g_degcnt[i] = 0; g_fill[i] = 0; g_tieflag[i] = 0; }
    if (i < 384) { g_gmax[i] = -3.402823466e38f; g_gsum[i] = 0.f; }
    if (i < 256) g_hist[i] = 0u;
    if (i == 0) { g_prefix = 0u; g_kprime = (unsigned)KKEEP; g_nties = 0; }
}

// ------------------------- B prep: split W[Kin,128] into fragment-major bf16 hi/lo ----
__global__ void k_prepB(const float *__restrict__ W, int Kin) {
    int i = blockIdx.x * blockDim.x + threadIdx.x;   // pair index
    if (i >= Kin * 64) return;
    int kp = i >> 7, n = i & 127;
    int k = kp * 2;
    float w0 = W[(size_t)k * 128 + n];
    float w1 = W[(size_t)(k + 1) * 128 + n];
    int c = k >> 5;
    int kk = k & 31;
    int nt = n >> 3, ks = kk >> 4;
    int r = ((kk & 15) >= 8) ? 1 : 0;
    int lane_b = (n & 7) * 4 + ((kk & 7) >> 1);
    int base = c * 2048 + ((nt * 2 + ks) * 32 + lane_b) * 2 + r;
    uint32_t h, l;
    split2_bf16(w0, w1, h, l);
    g_bhi[base] = h;
    g_blo[base] = l;
}

// ------------------------- degree / CSR build (edge_index is int32) -------------------------
__global__ void k_count(const int *__restrict__ ei) {
    int e4 = blockIdx.x * blockDim.x + threadIdx.x;
    if (e4 >= EE / 4) return;
    int4 d = *(const int4 *)&ei[EE + e4 * 4];
    atomicAdd(&g_degcnt[d.x], 1);
    atomicAdd(&g_degcnt[d.y], 1);
    atomicAdd(&g_degcnt[d.z], 1);
    atomicAdd(&g_degcnt[d.w], 1);
}
__global__ void k_chunksum() {
    __shared__ int sm[256];
    int t = threadIdx.x, b = blockIdx.x;
    int s = 0;
    for (int j = t; j < 1024; j += 256) {
        int idx = b * 1024 + j;
        if (idx < NN) s += g_degcnt[idx];
    }
    sm[t] = s; __syncthreads();
    for (int o = 128; o; o >>= 1) { if (t < o) sm[t] += sm[t + o]; __syncthreads(); }
    if (t == 0) g_chunksum[b] = sm[0];
}
__global__ void k_scanchunks() {
    int run = 0;
    for (int c = 0; c < NCH; ++c) { g_chunkoff[c] = run; run += g_chunksum[c]; }
    g_rowptr[NN] = EE;
}
__global__ void k_scanwrite() {
    __shared__ int sd[1024];
    int t = threadIdx.x, b = blockIdx.x;
    int idx = b * 1024 + t;
    int v = (idx < NN) ? g_degcnt[idx] : 0;
    int x = v;
    for (int o = 1; o < 1024; o <<= 1) {
        sd[t] = x; __syncthreads();
        if (t >= o) x += sd[t - o];
        __syncthreads();
    }
    if (idx < NN) g_rowptr[idx] = g_chunkoff[b] + x - v;
}
__global__ void k_scatter(const int *__restrict__ ei) {
    int e4 = blockIdx.x * blockDim.x + threadIdx.x;
    if (e4 >= EE / 4) return;
    int4 s = *(const int4 *)&ei[e4 * 4];
    int4 d = *(const int4 *)&ei[EE + e4 * 4];
    g_csr[g_rowptr[d.x] + atomicAdd(&g_fill[d.x], 1)] = s.x;
    g_csr[g_rowptr[d.y] + atomicAdd(&g_fill[d.y], 1)] = s.y;
    g_csr[g_rowptr[d.z] + atomicAdd(&g_fill[d.z], 1)] = s.z;
    g_csr[g_rowptr[d.w] + atomicAdd(&g_fill[d.w], 1)] = s.w;
}

// ------------------------- GEMM: cp.async pipeline carrying A (f32) + B hi/lo (bf16) ----
// CTA tile 128x128, BK=32 (2 k16 steps), 8 warps each 32x64 (warp grid 4M x 2N).
// Stage (32KB): [A f32 frag 16KB][Bhi 8KB][Blo 8KB], 3 stages.
// Epilogue: y = ds*(A@W) stored as half2 pairs into g_yh.
#define GPIPE 3
#define GSTAGE 32768
#define GT_SMEM_BYTES (GPIPE * GSTAGE)
__global__ __launch_bounds__(256, 2) void k_gemm_mma(const float *__restrict__ Aext, int useExt,
                                                     int whichSrc, int Kin) {
    extern __shared__ char smem[];
    const float *A = useExt ? Aext : pickX(whichSrc);
    uint32_t sbase = (uint32_t)__cvta_generic_to_shared(smem);

    int tid = threadIdx.x, wid = tid >> 5, lane = tid & 31;
    int wm = wid & 3, wn = wid >> 2;
    int row0 = blockIdx.x * 128;

    int cp_m[8], cp_dst[8];
    const float *cp_src[8];
#pragma unroll
    for (int it = 0; it < 8; ++it) {
        int i = tid + it * 256;
        int m = i >> 4, p = i & 15;
        int mt = m >> 4, ks = p >> 3;
        int l = (m & 7) * 4 + (p & 3);
        int off = 2 * (((m & 15) >= 8) ? 1 : 0) + 4 * (((p & 7) >= 4) ? 1 : 0);
        int fidx = ((mt * 2 + ks) * 32 + l) * 8 + off;
        cp_m[it] = m;
        cp_dst[it] = fidx * 4;
        cp_src[it] = A + (size_t)(row0 + m) * Kin + p * 2;
    }

    float acc[2][8][4];
#pragma unroll
    for (int mt = 0; mt < 2; ++mt)
#pragma unroll
        for (int nt = 0; nt < 8; ++nt)
#pragma unroll
            for (int q = 0; q < 4; ++q) acc[mt][nt][q] = 0.f;

    int nchunks = Kin >> 5;

    auto issue = [&](int c, int buf) {
        uint32_t bb = sbase + buf * GSTAGE;
#pragma unroll
        for (int it = 0; it < 8; ++it) {
            int valid = (row0 + cp_m[it] < NN) ? 8 : 0;
            CP_ASYNC8(bb + cp_dst[it], cp_src[it] + c * 32, valid);
        }
#pragma unroll
        for (int j = 0; j < 2; ++j) {
            int idx = tid + j * 256;
            CP_ASYNC16(bb + 16384 + idx * 16, (const char *)&g_bhi[c * 2048 + idx * 4]);
            CP_ASYNC16(bb + 24576 + idx * 16, (const char *)&g_blo[c * 2048 + idx * 4]);
        }
    };

    issue(0, 0); CP_COMMIT();
    issue(1, 1); CP_COMMIT();

    for (int c = 0; c < nchunks; ++c) {
        if (c + 1 < nchunks) { CP_WAIT1(); } else { CP_WAIT0(); }
        __syncthreads();
        if (c + 2 < nchunks) { issue(c + 2, (c + 2) % GPIPE); CP_COMMIT(); }

        const char *stg = smem + (c % GPIPE) * GSTAGE;
        const float *fa = (const float *)stg;
        const uint32_t *fbh = (const uint32_t *)(stg + 16384);
        const uint32_t *fbl = (const uint32_t *)(stg + 24576);
#pragma unroll
        for (int ks = 0; ks < 2; ++ks) {
            uint32_t ah[2][4], al[2][4];
#pragma unroll
            for (int mt = 0; mt < 2; ++mt) {
                int mtg = wm * 2 + mt;
                const float4 *p4 = (const float4 *)&fa[((mtg * 2 + ks) * 32 + lane) * 8];
                float4 u = p4[0], v = p4[1];
                split2_bf16(u.x, u.y, ah[mt][0], al[mt][0]);
                split2_bf16(u.z, u.w, ah[mt][1], al[mt][1]);
                split2_bf16(v.x, v.y, ah[mt][2], al[mt][2]);
                split2_bf16(v.z, v.w, ah[mt][3], al[mt][3]);
            }
#pragma unroll
            for (int nt = 0; nt < 8; ++nt) {
                int ntg = wn * 8 + nt;
                int bidx = ((ntg * 2 + ks) * 32 + lane) * 2;
                uint2 vh = *(const uint2 *)&fbh[bidx];
                uint2 vl = *(const uint2 *)&fbl[bidx];
                uint32_t bh[2] = {vh.x, vh.y};
                uint32_t bl[2] = {vl.x, vl.y};
#pragma unroll
                for (int mt = 0; mt < 2; ++mt) {
                    mma16816(acc[mt][nt], ah[mt], bh);
                    mma16816(acc[mt][nt], ah[mt], bl);
                    mma16816(acc[mt][nt], al[mt], bh);
                }
            }
        }
    }

    // ---- epilogue: y = ds*acc stored as half2 into g_yh ----
    int r = lane >> 2;
    int c2 = (lane & 3) * 2;      // even column offset
#pragma unroll
    for (int mt = 0; mt < 2; ++mt) {
        int rbase = row0 + wm * 32 + mt * 16 + r;
#pragma unroll
        for (int half = 0; half < 2; ++half) {
            int row = rbase + half * 8;
            if (row >= NN) continue;
            float sc = rsqrtf((float)(g_degcnt[row] + 1));
            uint32_t *dst = &g_yh[(size_t)row * 64 + wn * 32 + (lane & 3)];
#pragma unroll
            for (int nt = 0; nt < 8; ++nt) {
                half2 h = __floats2half2_rn(acc[mt][nt][half * 2 + 0] * sc,
                                            acc[mt][nt][half * 2 + 1] * sc);
                dst[nt * 4] = *(uint32_t *)&h;
            }
        }
    }
}

// ------------------------- aggregation: out = relu(ds[d]*(sum_nb y + y[d]) + b) -------------------------
// Gathers fp16 rows (256B), accumulates f32, writes f32 features.
__global__ __launch_bounds__(256) void k_agg(const float *__restrict__ bias, int whichDst) {
    int gw = (blockIdx.x * 256 + threadIdx.x) >> 5;
    int lane = threadIdx.x & 31;
    if (gw >= NN) return;
    float *out = (float *)pickX(whichDst);
    int start = g_rowptr[gw], end = g_rowptr[gw + 1];
    int cu = lane * 2;  // u32 index within 64-u32 row (= 4 floats)
    uint2 sv = *(const uint2 *)&g_yh[(size_t)gw * 64 + cu];
    float2 s0 = __half22float2(*(half2 *)&sv.x);
    float2 s1 = __half22float2(*(half2 *)&sv.y);
    float4 acc = make_float4(s0.x, s0.y, s1.x, s1.y);  // self term
    int e = start;
    for (; e + 4 <= end; e += 4) {
        int n0 = g_csr[e], n1 = g_csr[e + 1], n2 = g_csr[e + 2], n3 = g_csr[e + 3];
        uint2 v0 = *(const uint2 *)&g_yh[(size_t)n0 * 64 + cu];
        uint2 v1 = *(const uint2 *)&g_yh[(size_t)n1 * 64 + cu];
        uint2 v2 = *(const uint2 *)&g_yh[(size_t)n2 * 64 + cu];
        uint2 v3 = *(const uint2 *)&g_yh[(size_t)n3 * 64 + cu];
        float2 a0 = __half22float2(*(half2 *)&v0.x), b0 = __half22float2(*(half2 *)&v0.y);
        float2 a1 = __half22float2(*(half2 *)&v1.x), b1 = __half22float2(*(half2 *)&v1.y);
        float2 a2 = __half22float2(*(half2 *)&v2.x), b2 = __half22float2(*(half2 *)&v2.y);
        float2 a3 = __half22float2(*(half2 *)&v3.x), b3 = __half22float2(*(half2 *)&v3.y);
        acc.x += (a0.x + a1.x) + (a2.x + a3.x);
        acc.y += (a0.y + a1.y) + (a2.y + a3.y);
        acc.z += (b0.x + b1.x) + (b2.x + b3.x);
        acc.w += (b0.y + b1.y) + (b2.y + b3.y);
    }
    for (; e < end; ++e) {
        int n = g_csr[e];
        uint2 v = *(const uint2 *)&g_yh[(size_t)n * 64 + cu];
        float2 a = __half22float2(*(half2 *)&v.x), b = __half22float2(*(half2 *)&v.y);
        acc.x += a.x; acc.y += a.y; acc.z += b.x; acc.w += b.y;
    }
    float sc = rsqrtf((float)(g_degcnt[gw] + 1));
    float4 b4 = *(const float4 *)&bias[lane * 4];
    float4 o;
    o.x = fmaxf(fmaf(acc.x, sc, b4.x), 0.f);
    o.y = fmaxf(fmaf(acc.y, sc, b4.y), 0.f);
    o.z = fmaxf(fmaf(acc.z, sc, b4.z), 0.f);
    o.w = fmaxf(fmaf(acc.w, sc, b4.w), 0.f);
    *(float4 *)&out[(size_t)gw * 128 + lane * 4] = o;
}

// ------------------------- score: ys = ds * (cat . Ws), then GCN-aggregate scalar -------------------------
__global__ __launch_bounds__(256) void k_score_lin(const float *__restrict__ Ws) {
    __shared__ float sW[384];
    int tid = threadIdx.x;
    for (int i = tid; i < 384; i += 256) sW[i] = Ws[i];
    __syncthreads();
    int gw = (blockIdx.x * 256 + tid) >> 5;
    int lane = tid & 31;
    if (gw >= NN) return;
    size_t base = (size_t)gw * 128;
    float s = 0.f;
#pragma unroll
    for (int t = 0; t < 4; ++t) {
        int c = lane + 32 * t;
        s += g_x1[base + c] * sW[c] + g_x2[base + c] * sW[128 + c] + g_x3[base + c] * sW[256 + c];
    }
    for (int o = 16; o; o >>= 1) s += __shfl_down_sync(0xFFFFFFFFu, s, o);
    if (lane == 0) g_ysc[gw] = rsqrtf((float)(g_degcnt[gw] + 1)) * s;
}
__global__ __launch_bounds__(256) void k_score_agg(const float *__restrict__ bs) {
    int gw = (blockIdx.x * 256 + threadIdx.x) >> 5;
    int lane = threadIdx.x & 31;
    if (gw >= NN) return;
    int start = g_rowptr[gw], end = g_rowptr[gw + 1];
    float s = 0.f;
    for (int e = start + lane; e < end; e += 32) s += g_ysc[g_csr[e]];
    for (int o = 16; o; o >>= 1) s += __shfl_down_sync(0xFFFFFFFFu, s, o);
    if (lane == 0) {
        float tot = s + g_ysc[gw];
        float sc = fmaf(rsqrtf((float)(g_degcnt[gw] + 1)), tot, bs[0]);
        g_score[gw] = sc;
        g_ukey[gw] = fkey(sc);
    }
}

// ------------------------- radix select (4 passes of 8 bits) -------------------------
__global__ void k_hist(int pass) {
    __shared__ unsigned sh[256];
    int t = threadIdx.x;
    sh[t] = 0u; __syncthreads();
    int i = blockIdx.x * 256 + t;
    if (i < NN) {
        unsigned u = g_ukey[i];
        bool m = (pass == 0) || ((u >> (32 - 8 * pass)) == g_prefix);
        if (m) atomicAdd(&sh[(u >> (24 - 8 * pass)) & 255u], 1u);
    }
    __syncthreads();
    if (sh[t]) atomicAdd(&g_hist[t], sh[t]);
}
__global__ void k_select() {
    __shared__ unsigned h[256];
    int t = threadIdx.x;
    h[t] = g_hist[t];
    g_hist[t] = 0u;
    __syncthreads();
    if (t == 0) {
        unsigned kp = g_kprime, c = 0;
        int b;
        for (b = 255; b >= 0; --b) {
            if (c + h[b] >= kp) break;
            c += h[b];
        }
        if (b < 0) b = 0;
        g_prefix = (g_prefix << 8) | (unsigned)b;
        g_kprime = kp - c;
    }
}
__global__ void k_ties() {
    int i = blockIdx.x * blockDim.x + threadIdx.x;
    if (i >= NN) return;
    if (g_ukey[i] == g_prefix) {
        int p = atomicAdd(&g_nties, 1);
        g_tieidx[p] = i;
    }
}
__global__ void k_tieresolve() {
    int M = g_nties;
    unsigned R = g_kprime;
    for (int j = threadIdx.x; j < M; j += blockDim.x) {
        int idx = g_tieidx[j];
        unsigned rank = 0;
        for (int l = 0; l < M; ++l) rank += (g_tieidx[l] < idx) ? 1u : 0u;
        if (rank < R) g_tieflag[idx] = 1;
    }
}

// ------------------------- pooling (max + sum over kept nodes, 384 dims) -------------------------
__global__ __launch_bounds__(384) void k_pool() {
    int c = threadIdx.x;
    const float *xa = (c < 128) ? g_x1 : ((c < 256) ? g_x2 : g_x3);
    int cc = c & 127;
    unsigned T = g_prefix;
    float mx = -3.402823466e38f, sm = 0.f;
    for (int i = blockIdx.x; i < NN; i += gridDim.x) {
        unsigned u = g_ukey[i];
        if (u < T) continue;
        if (u == T && !g_tieflag[i]) continue;
        float g = tanhf(g_score[i]);
        float v = xa[(size_t)i * 128 + cc] * g;
        mx = fmaxf(mx, v);
        sm += v;
    }
    atomicMaxF(&g_gmax[c], mx);
    atomicAdd(&g_gsum[c], sm);
}

// ------------------------- final MLP head (single block) -------------------------
__global__ __launch_bounds__(128) void k_mlp(const float *__restrict__ Wl1, const float *__restrict__ bl1,
                                             const float *__restrict__ Wl2, const float *__restrict__ bl2,
                                             const float *__restrict__ Wl3, const float *__restrict__ bl3,
                                             float *__restrict__ out) {
    __shared__ float h[768], h1[128], h2[64], lg[10];
    int t = threadIdx.x;
    for (int c = t; c < 384; c += 128) {
        h[c] = g_gmax[c];
        h[384 + c] = g_gsum[c] * (1.0f / KKEEP);
    }
    __syncthreads();
    float s = bl1[t];
    for (int i = 0; i < 768; ++i) s = fmaf(h[i], Wl1[i * 128 + t], s);
    h1[t] = fmaxf(s, 0.f);
    __syncthreads();
    if (t < 64) {
        float s2 = bl2[t];
        for (int i = 0; i < 128; ++i) s2 = fmaf(h1[i], Wl2[i * 64 + t], s2);
        h2[t] = fmaxf(s2, 0.f);
    }
    __syncthreads();
    if (t < 10) {
        float s3 = bl3[t];
        for (int i = 0; i < 64; ++i) s3 = fmaf(h2[i], Wl3[i * 10 + t], s3);
        lg[t] = s3;
    }
    __syncthreads();
    if (t == 0) {
        float m = lg[0];
        for (int j = 1; j < 10; ++j) m = fmaxf(m, lg[j]);
        float se = 0.f;
        for (int j = 0; j < 10; ++j) se += expf(lg[j] - m);
        float lse = m + logf(se);
        for (int j = 0; j < 10; ++j) out[j] = lg[j] - lse;
    }
}

// ------------------------- launch -------------------------
extern "C" void kernel_launch(void *const *d_in, const int *in_sizes, int n_in,
                              void *d_out, int out_size) {
    const float *x      = (const float *)d_in[0];
    const int   *ei     = (const int *)d_in[1];   // int32
    const float *W1 = (const float *)d_in[3],  *b1  = (const float *)d_in[4];
    const float *W2 = (const float *)d_in[5],  *b2  = (const float *)d_in[6];
    const float *W3 = (const float *)d_in[7],  *b3  = (const float *)d_in[8];
    const float *Ws = (const float *)d_in[9],  *bs  = (const float *)d_in[10];
    const float *Wl1 = (const float *)d_in[11], *bl1 = (const float *)d_in[12];
    const float *Wl2 = (const float *)d_in[13], *bl2 = (const float *)d_in[14];
    const float *Wl3 = (const float *)d_in[15], *bl3 = (const float *)d_in[16];
    float *out = (float *)d_out;

    const int nblkN = (NN + 255) / 256;
    const int nblkE4 = (EE / 4 + 255) / 256;
    const int nblkW = (NN * 32 + 255) / 256;
    const int nblkT = (NN + 127) / 128;

    cudaFuncSetAttribute(k_gemm_mma, cudaFuncAttributeMaxDynamicSharedMemorySize, GT_SMEM_BYTES);

    // Prologue ordered so the ncu capture slot (4th launch) hits layer-1 gemm.
    k_init<<<nblkN, 256>>>();
    k_prepB<<<(FIN * 64 + 255) / 256, 256>>>(W1, FIN);
    k_count<<<nblkE4, 256>>>(ei);
    // GCN layer 1 GEMM
    k_gemm_mma<<<nblkT, 256, GT_SMEM_BYTES>>>(x, 1, 0, FIN);
    // CSR build
    k_chunksum<<<NCH, 256>>>();
    k_scanchunks<<<1, 1>>>();
    k_scanwrite<<<NCH, 1024>>>();
    k_scatter<<<nblkE4, 256>>>(ei);
    // GCN layer 1 aggregate
    k_agg<<<nblkW, 256>>>(b1, 1);
    // GCN layer 2
    k_prepB<<<(HH * 64 + 255) / 256, 256>>>(W2, HH);
    k_gemm_mma<<<nblkT, 256, GT_SMEM_BYTES>>>(nullptr, 0, 1, HH);
    k_agg<<<nblkW, 256>>>(b2, 2);
    // GCN layer 3
    k_prepB<<<(HH * 64 + 255) / 256, 256>>>(W3, HH);
    k_gemm_mma<<<nblkT, 256, GT_SMEM_BYTES>>>(nullptr, 0, 2, HH);
    k_agg<<<nblkW, 256>>>(b3, 3);
    // score GCN (1 channel)
    k_score_lin<<<nblkW, 256>>>(Ws);
    k_score_agg<<<nblkW, 256>>>(bs);
    // exact top-k threshold via 4x8-bit radix select
    for (int p = 0; p < 4; ++p) {
        k_hist<<<nblkN, 256>>>(p);
        k_select<<<1, 256>>>();
    }
    k_ties<<<nblkN, 256>>>();
    k_tieresolve<<<1, 256>>>();
    // gated max/mean readout over kept nodes
    k_pool<<<512, 384>>>();
    // MLP head + log_softmax
    k_mlp<<<1, 128>>>(Wl1, bl1, Wl2, bl2, Wl3, bl3, out);
}

// round 11
// speedup vs baseline: 2.1375x; 1.0847x over previous
#include <cuda_runtime.h>
#include <cuda_fp16.h>
#include <math.h>
#include <stdint.h>

#define NN 100000
#define EE 1600000
#define FIN 512
#define HH 128
#define KKEEP 50000
#define NCH 98  // ceil(NN/1024)

typedef unsigned long long ull;

// ------------------------- device scratch (globals) -------------------------
__device__ __align__(16) uint32_t g_yh[(size_t)NN * 64];  // y as half2 pairs (fp16 gather buffer)
__device__ __align__(16) float g_x1[(size_t)NN * HH];
__device__ __align__(16) float g_x2[(size_t)NN * HH];
__device__ __align__(16) float g_x3[(size_t)NN * HH];
__device__ int   g_degcnt[NN];
__device__ int   g_rowptr[NN + 1];
__device__ int   g_fill[NN];
__device__ int   g_csr[EE];
__device__ int   g_chunksum[NCH];
__device__ int   g_chunkoff[NCH];
__device__ float g_ysc[NN];
__device__ float g_score[NN];
__device__ unsigned g_ukey[NN];
__device__ unsigned g_hist[256];
__device__ unsigned g_prefix;
__device__ unsigned g_kprime;
__device__ int   g_nties;
__device__ int   g_tieidx[NN];
__device__ int   g_tieflag[NN];
__device__ float g_gmax[384];
__device__ float g_gsum[384];
// pre-split B (W^T) fragments per layer, bf16 hi/lo, chunk-major: [layer][chunk][2048]
__device__ __align__(16) uint32_t g_bhi[3 * 16 * 2048];
__device__ __align__(16) uint32_t g_blo[3 * 16 * 2048];

// ------------------------- small helpers -------------------------
__device__ __forceinline__ unsigned fkey(float f) {
    unsigned u = __float_as_uint(f);
    return (u & 0x80000000u) ? ~u : (u | 0x80000000u);
}
__device__ __forceinline__ void atomicMaxF(float *addr, float val) {
    if (val >= 0.f) atomicMax((int *)addr, __float_as_int(val));
    else            atomicMin((unsigned *)addr, __float_as_uint(val));
}
__device__ __forceinline__ const float *pickX(int w) {
    return w == 1 ? g_x1 : (w == 2 ? g_x2 : g_x3);
}
__device__ __forceinline__ uint32_t pack_bf16x2(float x, float y) {
    uint32_t r;
    asm("cvt.rn.bf16x2.f32 %0, %1, %2;" : "=r"(r) : "f"(y), "f"(x));
    return r;
}
__device__ __forceinline__ float bf16lo_f(uint32_t p) { return __uint_as_float(p << 16); }
__device__ __forceinline__ float bf16hi_f(uint32_t p) { return __uint_as_float(p & 0xFFFF0000u); }
__device__ __forceinline__ void split2_bf16(float x, float y, uint32_t &hi, uint32_t &lo) {
    hi = pack_bf16x2(x, y);
    lo = pack_bf16x2(x - bf16lo_f(hi), y - bf16hi_f(hi));
}
__device__ __forceinline__ void mma16816(float *d, const uint32_t *a, const uint32_t *b) {
    asm volatile("mma.sync.aligned.m16n8k16.row.col.f32.bf16.bf16.f32 "
                 "{%0,%1,%2,%3}, {%4,%5,%6,%7}, {%8,%9}, {%0,%1,%2,%3};"
                 : "+f"(d[0]), "+f"(d[1]), "+f"(d[2]), "+f"(d[3])
                 : "r"(a[0]), "r"(a[1]), "r"(a[2]), "r"(a[3]), "r"(b[0]), "r"(b[1]));
}
#define CP_ASYNC8(dst_u32, src_ptr, szreg) \
    asm volatile("cp.async.ca.shared.global [%0], [%1], 8, %2;" \
                 :: "r"(dst_u32), "l"(src_ptr), "r"(szreg))
#define CP_ASYNC16(dst_u32, src_ptr) \
    asm volatile("cp.async.cg.shared.global [%0], [%1], 16;" \
                 :: "r"(dst_u32), "l"(src_ptr))
#define CP_COMMIT() asm volatile("cp.async.commit_group;" ::: "memory")
#define CP_WAIT1() asm volatile("cp.async.wait_group 1;" ::: "memory")
#define CP_WAIT0() asm volatile("cp.async.wait_group 0;" ::: "memory")

// ------------------------- init -------------------------
__global__ void k_init() {
    int i = blockIdx.x * blockDim.x + threadIdx.x;
    if (i < NN) { g_degcnt[i] = 0; g_fill[i] = 0; g_tieflag[i] = 0; }
    if (i < 384) { g_gmax[i] = -3.402823466e38f; g_gsum[i] = 0.f; }
    if (i < 256) g_hist[i] = 0u;
    if (i == 0) { g_prefix = 0u; g_kprime = (unsigned)KKEEP; g_nties = 0; }
}

// ------------------------- B prep: split W[Kin,128] into fragment-major bf16 hi/lo ----
__global__ void k_prepB(const float *__restrict__ W, int Kin, int layer) {
    int i = blockIdx.x * blockDim.x + threadIdx.x;   // pair index
    if (i >= Kin * 64) return;
    int kp = i >> 7, n = i & 127;
    int k = kp * 2;
    float w0 = W[(size_t)k * 128 + n];
    float w1 = W[(size_t)(k + 1) * 128 + n];
    int c = k >> 5;
    int kk = k & 31;
    int nt = n >> 3, ks = kk >> 4;
    int r = ((kk & 15) >= 8) ? 1 : 0;
    int lane_b = (n & 7) * 4 + ((kk & 7) >> 1);
    int base = layer * 32768 + c * 2048 + ((nt * 2 + ks) * 32 + lane_b) * 2 + r;
    uint32_t h, l;
    split2_bf16(w0, w1, h, l);
    g_bhi[base] = h;
    g_blo[base] = l;
}

// ------------------------- degree / CSR build (edge_index is int32) -------------------------
__global__ void k_count(const int *__restrict__ ei) {
    int e4 = blockIdx.x * blockDim.x + threadIdx.x;
    if (e4 >= EE / 4) return;
    int4 d = *(const int4 *)&ei[EE + e4 * 4];
    atomicAdd(&g_degcnt[d.x], 1);
    atomicAdd(&g_degcnt[d.y], 1);
    atomicAdd(&g_degcnt[d.z], 1);
    atomicAdd(&g_degcnt[d.w], 1);
}
__global__ void k_chunksum() {
    __shared__ int sm[256];
    int t = threadIdx.x, b = blockIdx.x;
    int s = 0;
    for (int j = t; j < 1024; j += 256) {
        int idx = b * 1024 + j;
        if (idx < NN) s += g_degcnt[idx];
    }
    sm[t] = s; __syncthreads();
    for (int o = 128; o; o >>= 1) { if (t < o) sm[t] += sm[t + o]; __syncthreads(); }
    if (t == 0) g_chunksum[b] = sm[0];
}
__global__ void k_scanchunks() {
    int run = 0;
    for (int c = 0; c < NCH; ++c) { g_chunkoff[c] = run; run += g_chunksum[c]; }
    g_rowptr[NN] = EE;
}
__global__ void k_scanwrite() {
    __shared__ int sd[1024];
    int t = threadIdx.x, b = blockIdx.x;
    int idx = b * 1024 + t;
    int v = (idx < NN) ? g_degcnt[idx] : 0;
    int x = v;
    for (int o = 1; o < 1024; o <<= 1) {
        sd[t] = x; __syncthreads();
        if (t >= o) x += sd[t - o];
        __syncthreads();
    }
    if (idx < NN) g_rowptr[idx] = g_chunkoff[b] + x - v;
}
__global__ void k_scatter(const int *__restrict__ ei) {
    int e4 = blockIdx.x * blockDim.x + threadIdx.x;
    if (e4 >= EE / 4) return;
    int4 s = *(const int4 *)&ei[e4 * 4];
    int4 d = *(const int4 *)&ei[EE + e4 * 4];
    g_csr[g_rowptr[d.x] + atomicAdd(&g_fill[d.x], 1)] = s.x;
    g_csr[g_rowptr[d.y] + atomicAdd(&g_fill[d.y], 1)] = s.y;
    g_csr[g_rowptr[d.z] + atomicAdd(&g_fill[d.z], 1)] = s.z;
    g_csr[g_rowptr[d.w] + atomicAdd(&g_fill[d.w], 1)] = s.w;
}

// ------------------------- GEMM: cp.async pipeline carrying A (f32) + B hi/lo (bf16) ----
// CTA tile 128x128, BK=32 (2 k16 steps), 8 warps each 32x64 (warp grid 4M x 2N).
// Stage (32KB): [A f32 frag 16KB][Bhi 8KB][Blo 8KB], 3 stages.
// Epilogue: y = ds*(A@W) stored as half2 pairs into g_yh.
#define GPIPE 3
#define GSTAGE 32768
#define GT_SMEM_BYTES (GPIPE * GSTAGE)
__global__ __launch_bounds__(256, 2) void k_gemm_mma(const float *__restrict__ Aext, int useExt,
                                                     int whichSrc, int Kin, int layer) {
    extern __shared__ char smem[];
    const float *A = useExt ? Aext : pickX(whichSrc);
    uint32_t sbase = (uint32_t)__cvta_generic_to_shared(smem);
    const uint32_t *bhi = g_bhi + layer * 32768;
    const uint32_t *blo = g_blo + layer * 32768;

    int tid = threadIdx.x, wid = tid >> 5, lane = tid & 31;
    int wm = wid & 3, wn = wid >> 2;
    int row0 = blockIdx.x * 128;

    int cp_m[8], cp_dst[8];
    const float *cp_src[8];
#pragma unroll
    for (int it = 0; it < 8; ++it) {
        int i = tid + it * 256;
        int m = i >> 4, p = i & 15;
        int mt = m >> 4, ks = p >> 3;
        int l = (m & 7) * 4 + (p & 3);
        int off = 2 * (((m & 15) >= 8) ? 1 : 0) + 4 * (((p & 7) >= 4) ? 1 : 0);
        int fidx = ((mt * 2 + ks) * 32 + l) * 8 + off;
        cp_m[it] = m;
        cp_dst[it] = fidx * 4;
        cp_src[it] = A + (size_t)(row0 + m) * Kin + p * 2;
    }

    float acc[2][8][4];
#pragma unroll
    for (int mt = 0; mt < 2; ++mt)
#pragma unroll
        for (int nt = 0; nt < 8; ++nt)
#pragma unroll
            for (int q = 0; q < 4; ++q) acc[mt][nt][q] = 0.f;

    int nchunks = Kin >> 5;

    auto issue = [&](int c, int buf) {
        uint32_t bb = sbase + buf * GSTAGE;
#pragma unroll
        for (int it = 0; it < 8; ++it) {
            int valid = (row0 + cp_m[it] < NN) ? 8 : 0;
            CP_ASYNC8(bb + cp_dst[it], cp_src[it] + c * 32, valid);
        }
#pragma unroll
        for (int j = 0; j < 2; ++j) {
            int idx = tid + j * 256;
            CP_ASYNC16(bb + 16384 + idx * 16, (const char *)&bhi[c * 2048 + idx * 4]);
            CP_ASYNC16(bb + 24576 + idx * 16, (const char *)&blo[c * 2048 + idx * 4]);
        }
    };

    issue(0, 0); CP_COMMIT();
    issue(1, 1); CP_COMMIT();

    for (int c = 0; c < nchunks; ++c) {
        if (c + 1 < nchunks) { CP_WAIT1(); } else { CP_WAIT0(); }
        __syncthreads();
        if (c + 2 < nchunks) { issue(c + 2, (c + 2) % GPIPE); CP_COMMIT(); }

        const char *stg = smem + (c % GPIPE) * GSTAGE;
        const float *fa = (const float *)stg;
        const uint32_t *fbh = (const uint32_t *)(stg + 16384);
        const uint32_t *fbl = (const uint32_t *)(stg + 24576);
#pragma unroll
        for (int ks = 0; ks < 2; ++ks) {
            uint32_t ah[2][4], al[2][4];
#pragma unroll
            for (int mt = 0; mt < 2; ++mt) {
                int mtg = wm * 2 + mt;
                const float4 *p4 = (const float4 *)&fa[((mtg * 2 + ks) * 32 + lane) * 8];
                float4 u = p4[0], v = p4[1];
                split2_bf16(u.x, u.y, ah[mt][0], al[mt][0]);
                split2_bf16(u.z, u.w, ah[mt][1], al[mt][1]);
                split2_bf16(v.x, v.y, ah[mt][2], al[mt][2]);
                split2_bf16(v.z, v.w, ah[mt][3], al[mt][3]);
            }
#pragma unroll
            for (int nt = 0; nt < 8; ++nt) {
                int ntg = wn * 8 + nt;
                int bidx = ((ntg * 2 + ks) * 32 + lane) * 2;
                uint2 vh = *(const uint2 *)&fbh[bidx];
                uint2 vl = *(const uint2 *)&fbl[bidx];
                uint32_t bh[2] = {vh.x, vh.y};
                uint32_t bl[2] = {vl.x, vl.y};
#pragma unroll
                for (int mt = 0; mt < 2; ++mt) {
                    mma16816(acc[mt][nt], ah[mt], bh);
                    mma16816(acc[mt][nt], ah[mt], bl);
                    mma16816(acc[mt][nt], al[mt], bh);
                }
            }
        }
    }

    // ---- epilogue: y = ds*acc stored as half2 into g_yh ----
    int r = lane >> 2;
#pragma unroll
    for (int mt = 0; mt < 2; ++mt) {
        int rbase = row0 + wm * 32 + mt * 16 + r;
#pragma unroll
        for (int half = 0; half < 2; ++half) {
            int row = rbase + half * 8;
            if (row >= NN) continue;
            float sc = rsqrtf((float)(g_degcnt[row] + 1));
            uint32_t *dst = &g_yh[(size_t)row * 64 + wn * 32 + (lane & 3)];
#pragma unroll
            for (int nt = 0; nt < 8; ++nt) {
                half2 h = __floats2half2_rn(acc[mt][nt][half * 2 + 0] * sc,
                                            acc[mt][nt][half * 2 + 1] * sc);
                dst[nt * 4] = *(uint32_t *)&h;
            }
        }
    }
}

// ------------------------- aggregation: out = relu(ds[d]*(sum_nb y + y[d]) + b) -------------------------
// Gathers fp16 rows (256B), accumulates f32, writes f32 features.
// For layer 3 (fuseScore=1): also computes ysc[gw] = ds * dot(cat(x1,x2,x3), Ws).
__global__ __launch_bounds__(256) void k_agg(const float *__restrict__ bias, int whichDst,
                                             int fuseScore, const float *__restrict__ Ws) {
    int gw = (blockIdx.x * 256 + threadIdx.x) >> 5;
    int lane = threadIdx.x & 31;
    if (gw >= NN) return;
    float *out = (float *)pickX(whichDst);
    int start = g_rowptr[gw], end = g_rowptr[gw + 1];
    int cu = lane * 2;  // u32 index within 64-u32 row (= 4 floats)
    uint2 sv = *(const uint2 *)&g_yh[(size_t)gw * 64 + cu];
    float2 s0 = __half22float2(*(half2 *)&sv.x);
    float2 s1 = __half22float2(*(half2 *)&sv.y);
    float4 acc = make_float4(s0.x, s0.y, s1.x, s1.y);  // self term
    int e = start;
    for (; e + 4 <= end; e += 4) {
        int n0 = g_csr[e], n1 = g_csr[e + 1], n2 = g_csr[e + 2], n3 = g_csr[e + 3];
        uint2 v0 = *(const uint2 *)&g_yh[(size_t)n0 * 64 + cu];
        uint2 v1 = *(const uint2 *)&g_yh[(size_t)n1 * 64 + cu];
        uint2 v2 = *(const uint2 *)&g_yh[(size_t)n2 * 64 + cu];
        uint2 v3 = *(const uint2 *)&g_yh[(size_t)n3 * 64 + cu];
        float2 a0 = __half22float2(*(half2 *)&v0.x), b0 = __half22float2(*(half2 *)&v0.y);
        float2 a1 = __half22float2(*(half2 *)&v1.x), b1 = __half22float2(*(half2 *)&v1.y);
        float2 a2 = __half22float2(*(half2 *)&v2.x), b2 = __half22float2(*(half2 *)&v2.y);
        float2 a3 = __half22float2(*(half2 *)&v3.x), b3 = __half22float2(*(half2 *)&v3.y);
        acc.x += (a0.x + a1.x) + (a2.x + a3.x);
        acc.y += (a0.y + a1.y) + (a2.y + a3.y);
        acc.z += (b0.x + b1.x) + (b2.x + b3.x);
        acc.w += (b0.y + b1.y) + (b2.y + b3.y);
    }
    for (; e < end; ++e) {
        int n = g_csr[e];
        uint2 v = *(const uint2 *)&g_yh[(size_t)n * 64 + cu];
        float2 a = __half22float2(*(half2 *)&v.x), b = __half22float2(*(half2 *)&v.y);
        acc.x += a.x; acc.y += a.y; acc.z += b.x; acc.w += b.y;
    }
    float sc = rsqrtf((float)(g_degcnt[gw] + 1));
    int c0 = lane * 4;
    float4 b4 = *(const float4 *)&bias[c0];
    float4 o;
    o.x = fmaxf(fmaf(acc.x, sc, b4.x), 0.f);
    o.y = fmaxf(fmaf(acc.y, sc, b4.y), 0.f);
    o.z = fmaxf(fmaf(acc.z, sc, b4.z), 0.f);
    o.w = fmaxf(fmaf(acc.w, sc, b4.w), 0.f);
    *(float4 *)&out[(size_t)gw * 128 + c0] = o;

    if (fuseScore) {
        // score partial: dot(x1,Ws[0:128]) + dot(x2,Ws[128:256]) + dot(x3=o,Ws[256:384])
        float4 w1 = *(const float4 *)&Ws[c0];
        float4 w2 = *(const float4 *)&Ws[128 + c0];
        float4 w3 = *(const float4 *)&Ws[256 + c0];
        float4 x1v = *(const float4 *)&g_x1[(size_t)gw * 128 + c0];
        float4 x2v = *(const float4 *)&g_x2[(size_t)gw * 128 + c0];
        float s = x1v.x * w1.x + x1v.y * w1.y + x1v.z * w1.z + x1v.w * w1.w
                + x2v.x * w2.x + x2v.y * w2.y + x2v.z * w2.z + x2v.w * w2.w
                + o.x * w3.x + o.y * w3.y + o.z * w3.z + o.w * w3.w;
        for (int off = 16; off; off >>= 1) s += __shfl_down_sync(0xFFFFFFFFu, s, off);
        if (lane == 0) g_ysc[gw] = sc * s;
    }
}

// ------------------------- score aggregate (scalar GCN) -------------------------
__global__ __launch_bounds__(256) void k_score_agg(const float *__restrict__ bs) {
    int gw = (blockIdx.x * 256 + threadIdx.x) >> 5;
    int lane = threadIdx.x & 31;
    if (gw >= NN) return;
    int start = g_rowptr[gw], end = g_rowptr[gw + 1];
    float s = 0.f;
    for (int e = start + lane; e < end; e += 32) s += g_ysc[g_csr[e]];
    for (int o = 16; o; o >>= 1) s += __shfl_down_sync(0xFFFFFFFFu, s, o);
    if (lane == 0) {
        float tot = s + g_ysc[gw];
        float sc = fmaf(rsqrtf((float)(g_degcnt[gw] + 1)), tot, bs[0]);
        g_score[gw] = sc;
        g_ukey[gw] = fkey(sc);
    }
}

// ------------------------- radix select (4 passes of 8 bits) -------------------------
__global__ void k_hist(int pass) {
    __shared__ unsigned sh[256];
    int t = threadIdx.x;
    sh[t] = 0u; __syncthreads();
    int i = blockIdx.x * 256 + t;
    if (i < NN) {
        unsigned u = g_ukey[i];
        bool m = (pass == 0) || ((u >> (32 - 8 * pass)) == g_prefix);
        if (m) atomicAdd(&sh[(u >> (24 - 8 * pass)) & 255u], 1u);
    }
    __syncthreads();
    if (sh[t]) atomicAdd(&g_hist[t], sh[t]);
}
__global__ void k_select() {
    __shared__ unsigned h[256];
    int t = threadIdx.x;
    h[t] = g_hist[t];
    g_hist[t] = 0u;
    __syncthreads();
    if (t == 0) {
        unsigned kp = g_kprime, c = 0;
        int b;
        for (b = 255; b >= 0; --b) {
            if (c + h[b] >= kp) break;
            c += h[b];
        }
        if (b < 0) b = 0;
        g_prefix = (g_prefix << 8) | (unsigned)b;
        g_kprime = kp - c;
    }
}
__global__ void k_ties() {
    int i = blockIdx.x * blockDim.x + threadIdx.x;
    if (i >= NN) return;
    if (g_ukey[i] == g_prefix) {
        int p = atomicAdd(&g_nties, 1);
        g_tieidx[p] = i;
    }
}
__global__ void k_tieresolve() {
    int M = g_nties;
    unsigned R = g_kprime;
    for (int j = threadIdx.x; j < M; j += blockDim.x) {
        int idx = g_tieidx[j];
        unsigned rank = 0;
        for (int l = 0; l < M; ++l) rank += (g_tieidx[l] < idx) ? 1u : 0u;
        if (rank < R) g_tieflag[idx] = 1;
    }
}

// ------------------------- pooling (max + sum over kept nodes, 384 dims) -------------------------
__global__ __launch_bounds__(384) void k_pool() {
    int c = threadIdx.x;
    const float *xa = (c < 128) ? g_x1 : ((c < 256) ? g_x2 : g_x3);
    int cc = c & 127;
    unsigned T = g_prefix;
    float mx = -3.402823466e38f, sm = 0.f;
    for (int i = blockIdx.x; i < NN; i += gridDim.x) {
        unsigned u = g_ukey[i];
        if (u < T) continue;
        if (u == T && !g_tieflag[i]) continue;
        float g = tanhf(g_score[i]);
        float v = xa[(size_t)i * 128 + cc] * g;
        mx = fmaxf(mx, v);
        sm += v;
    }
    atomicMaxF(&g_gmax[c], mx);
    atomicAdd(&g_gsum[c], sm);
}

// ------------------------- final MLP head (single block) -------------------------
__global__ __launch_bounds__(128) void k_mlp(const float *__restrict__ Wl1, const float *__restrict__ bl1,
                                             const float *__restrict__ Wl2, const float *__restrict__ bl2,
                                             const float *__restrict__ Wl3, const float *__restrict__ bl3,
                                             float *__restrict__ out) {
    __shared__ float h[768], h1[128], h2[64], lg[10];
    int t = threadIdx.x;
    for (int c = t; c < 384; c += 128) {
        h[c] = g_gmax[c];
        h[384 + c] = g_gsum[c] * (1.0f / KKEEP);
    }
    __syncthreads();
    float s = bl1[t];
    for (int i = 0; i < 768; ++i) s = fmaf(h[i], Wl1[i * 128 + t], s);
    h1[t] = fmaxf(s, 0.f);
    __syncthreads();
    if (t < 64) {
        float s2 = bl2[t];
        for (int i = 0; i < 128; ++i) s2 = fmaf(h1[i], Wl2[i * 64 + t], s2);
        h2[t] = fmaxf(s2, 0.f);
    }
    __syncthreads();
    if (t < 10) {
        float s3 = bl3[t];
        for (int i = 0; i < 64; ++i) s3 = fmaf(h2[i], Wl3[i * 10 + t], s3);
        lg[t] = s3;
    }
    __syncthreads();
    if (t == 0) {
        float m = lg[0];
        for (int j = 1; j < 10; ++j) m = fmaxf(m, lg[j]);
        float se = 0.f;
        for (int j = 0; j < 10; ++j) se += expf(lg[j] - m);
        float lse = m + logf(se);
        for (int j = 0; j < 10; ++j) out[j] = lg[j] - lse;
    }
}

// ------------------------- launch -------------------------
extern "C" void kernel_launch(void *const *d_in, const int *in_sizes, int n_in,
                              void *d_out, int out_size) {
    const float *x      = (const float *)d_in[0];
    const int   *ei     = (const int *)d_in[1];   // int32
    const float *W1 = (const float *)d_in[3],  *b1  = (const float *)d_in[4];
    const float *W2 = (const float *)d_in[5],  *b2  = (const float *)d_in[6];
    const float *W3 = (const float *)d_in[7],  *b3  = (const float *)d_in[8];
    const float *Ws = (const float *)d_in[9],  *bs  = (const float *)d_in[10];
    const float *Wl1 = (const float *)d_in[11], *bl1 = (const float *)d_in[12];
    const float *Wl2 = (const float *)d_in[13], *bl2 = (const float *)d_in[14];
    const float *Wl3 = (const float *)d_in[15], *bl3 = (const float *)d_in[16];
    float *out = (float *)d_out;

    const int nblkN = (NN + 255) / 256;
    const int nblkE4 = (EE / 4 + 255) / 256;
    const int nblkW = (NN * 32 + 255) / 256;
    const int nblkT = (NN + 127) / 128;

    // streams/events created once on first (non-capture) call
    static cudaStream_t sCsr = nullptr, sPrep = nullptr;
    static cudaEvent_t evFork = nullptr, evCsr = nullptr, evPrep = nullptr;
    static bool inited = false;
    if (!inited) {
        cudaStreamCreateWithFlags(&sCsr, cudaStreamNonBlocking);
        cudaStreamCreateWithFlags(&sPrep, cudaStreamNonBlocking);
        cudaEventCreateWithFlags(&evFork, cudaEventDisableTiming);
        cudaEventCreateWithFlags(&evCsr, cudaEventDisableTiming);
        cudaEventCreateWithFlags(&evPrep, cudaEventDisableTiming);
        cudaFuncSetAttribute(k_gemm_mma, cudaFuncAttributeMaxDynamicSharedMemorySize, GT_SMEM_BYTES);
        inited = true;
    }

    // ---- origin stream: init, prepB layer0, degree count ----
    k_init<<<nblkN, 256>>>();
    k_prepB<<<(FIN * 64 + 255) / 256, 256>>>(W1, FIN, 0);
    k_count<<<nblkE4, 256>>>(ei);
    cudaEventRecord(evFork, 0);

    // ---- side stream 1: CSR build (overlaps GEMM-1) ----
    cudaStreamWaitEvent(sCsr, evFork, 0);
    k_chunksum<<<NCH, 256, 0, sCsr>>>();
    k_scanchunks<<<1, 1, 0, sCsr>>>();
    k_scanwrite<<<NCH, 1024, 0, sCsr>>>();
    k_scatter<<<nblkE4, 256, 0, sCsr>>>(ei);
    cudaEventRecord(evCsr, sCsr);

    // ---- side stream 2: prepB layers 1,2 ----
    cudaStreamWaitEvent(sPrep, evFork, 0);
    k_prepB<<<(HH * 64 + 255) / 256, 256, 0, sPrep>>>(W2, HH, 1);
    k_prepB<<<(HH * 64 + 255) / 256, 256, 0, sPrep>>>(W3, HH, 2);
    cudaEventRecord(evPrep, sPrep);

    // ---- origin: GCN layer 1 GEMM (concurrent with CSR build) ----
    k_gemm_mma<<<nblkT, 256, GT_SMEM_BYTES>>>(x, 1, 0, FIN, 0);
    cudaStreamWaitEvent(0, evCsr, 0);
    k_agg<<<nblkW, 256>>>(b1, 1, 0, nullptr);
    // layer 2
    cudaStreamWaitEvent(0, evPrep, 0);
    k_gemm_mma<<<nblkT, 256, GT_SMEM_BYTES>>>(nullptr, 0, 1, HH, 1);
    k_agg<<<nblkW, 256>>>(b2, 2, 0, nullptr);
    // layer 3 (+fused score linear)
    k_gemm_mma<<<nblkT, 256, GT_SMEM_BYTES>>>(nullptr, 0, 2, HH, 2);
    k_agg<<<nblkW, 256>>>(b3, 3, 1, Ws);
    // score aggregate
    k_score_agg<<<nblkW, 256>>>(bs);
    // exact top-k threshold via 4x8-bit radix select
    for (int p = 0; p < 4; ++p) {
        k_hist<<<nblkN, 256>>>(p);
        k_select<<<1, 256>>>();
    }
    k_ties<<<nblkN, 256>>>();
    k_tieresolve<<<1, 256>>>();
    // gated max/mean readout over kept nodes
    k_pool<<<512, 384>>>();
    // MLP head + log_softmax
    k_mlp<<<1, 128>>>(Wl1, bl1, Wl2, bl2, Wl3, bl3, out);
}